// round 1
// baseline (speedup 1.0000x reference)
#include <cuda_runtime.h>
#include <math.h>

#define N_NODES 50000
#define N_EDGES 300000
#define ANNOT   200
#define HID     256
#define N_STEPS 8

// ---------------- scratch (static device globals; no runtime alloc) ----------
__device__ float g_h  [N_NODES * HID];
__device__ float g_m  [N_NODES * HID];
__device__ float g_agg[N_NODES * HID];
__device__ float g_gi [N_NODES * 3 * HID];
__device__ float g_gh [N_NODES * 3 * HID];

// ---------------- tiled SGEMM ------------------------------------------------
// BT=true : C[M,N] = A[M,K] @ B[N,K]^T + bias   (B row-major [N,K], K contiguous)
// BT=false: C[M,N] = A[M,K] @ B[K,N]   + bias   (B row-major [K,N], N contiguous)
// Requirements: K % 8 == 0, N % 128 == 0 (true for all calls here). M guarded.
template <bool BT>
__global__ void __launch_bounds__(256)
sgemm_kernel(const float* __restrict__ A, const float* __restrict__ B,
             const float* __restrict__ bias, float* __restrict__ C,
             int M, int N, int K)
{
    __shared__ float As[8][128];
    __shared__ float Bs[8][128];

    const int tid = threadIdx.x;
    const int tx  = tid & 15;       // 0..15 -> col group
    const int ty  = tid >> 4;       // 0..15 -> row group
    const int row0 = blockIdx.y * 128;
    const int col0 = blockIdx.x * 128;

    float acc[8][8];
#pragma unroll
    for (int i = 0; i < 8; i++)
#pragma unroll
        for (int j = 0; j < 8; j++) acc[i][j] = 0.0f;

    // K-contiguous load pattern (A always, B when BT)
    const int a_r = tid >> 1;           // 0..127
    const int a_c = (tid & 1) * 4;      // 0 or 4
    // N-contiguous load pattern (B when !BT)
    const int b_k = tid >> 5;           // 0..7
    const int b_n = (tid & 31) * 4;     // 0..124

    for (int k0 = 0; k0 < K; k0 += 8) {
        // ---- load A tile (transposed into As[k][m]) ----
        float4 av = make_float4(0.f, 0.f, 0.f, 0.f);
        const int arow = row0 + a_r;
        if (arow < M)
            av = *(const float4*)(A + (size_t)arow * K + k0 + a_c);
        As[a_c + 0][a_r] = av.x;
        As[a_c + 1][a_r] = av.y;
        As[a_c + 2][a_r] = av.z;
        As[a_c + 3][a_r] = av.w;

        // ---- load B tile into Bs[k][n] ----
        if (BT) {
            const int brow = col0 + a_r;   // output column index, always < N
            float4 bv = *(const float4*)(B + (size_t)brow * K + k0 + a_c);
            Bs[a_c + 0][a_r] = bv.x;
            Bs[a_c + 1][a_r] = bv.y;
            Bs[a_c + 2][a_r] = bv.z;
            Bs[a_c + 3][a_r] = bv.w;
        } else {
            float4 bv = *(const float4*)(B + (size_t)(k0 + b_k) * N + col0 + b_n);
            *(float4*)&Bs[b_k][b_n] = bv;
        }
        __syncthreads();

#pragma unroll
        for (int k = 0; k < 8; k++) {
            float ar8[8], br8[8];
#pragma unroll
            for (int i = 0; i < 8; i++) ar8[i] = As[k][ty * 8 + i];
#pragma unroll
            for (int j = 0; j < 8; j++) br8[j] = Bs[k][tx * 8 + j];
#pragma unroll
            for (int i = 0; i < 8; i++)
#pragma unroll
                for (int j = 0; j < 8; j++)
                    acc[i][j] = fmaf(ar8[i], br8[j], acc[i][j]);
        }
        __syncthreads();
    }

    // ---- epilogue ----
#pragma unroll
    for (int i = 0; i < 8; i++) {
        const int r = row0 + ty * 8 + i;
        if (r >= M) break;
        float* crow = C + (size_t)r * N + col0 + tx * 8;
#pragma unroll
        for (int j = 0; j < 8; j++) {
            float v = acc[i][j];
            if (bias) v += bias[col0 + tx * 8 + j];
            crow[j] = v;
        }
    }
}

// ---------------- scatter-add: agg[dst[e]] += m[src[e]] ---------------------
// one thread per (edge, 4 columns); threads in a warp cover consecutive cols.
__global__ void scatter_kernel(const float* __restrict__ m,
                               const int* __restrict__ ei,
                               float* __restrict__ agg, int E)
{
    const int idx = blockIdx.x * blockDim.x + threadIdx.x;
    if (idx >= E * (HID / 4)) return;
    const int e  = idx >> 6;          // HID/4 = 64
    const int c4 = idx & 63;
    const int s = ei[e];
    const int d = ei[E + e];
    float4 v = *(const float4*)(m + (size_t)s * HID + c4 * 4);
    float* o = agg + (size_t)d * HID + c4 * 4;
    atomicAdd(o + 0, v.x);
    atomicAdd(o + 1, v.y);
    atomicAdd(o + 2, v.z);
    atomicAdd(o + 3, v.w);
}

// ---------------- fused GRU gates (in-place update of h) ---------------------
__device__ __forceinline__ float sigf(float x) { return 1.0f / (1.0f + __expf(-x)); }

__global__ void gru_kernel(const float* __restrict__ gi,
                           const float* __restrict__ gh,
                           float* __restrict__ h, int N)
{
    const int idx = blockIdx.x * blockDim.x + threadIdx.x;
    if (idx >= N * (HID / 4)) return;
    const int row = idx >> 6;
    const int c4  = idx & 63;
    const float4* GI = (const float4*)(gi + (size_t)row * 3 * HID);
    const float4* GH = (const float4*)(gh + (size_t)row * 3 * HID);
    float4 ir = GI[c4], iz = GI[64 + c4], in = GI[128 + c4];
    float4 hr = GH[c4], hz = GH[64 + c4], hn = GH[128 + c4];
    float4* H = (float4*)(h + (size_t)row * HID);
    float4 hv = H[c4];

    float4 o;
    {
        float r = sigf(ir.x + hr.x), z = sigf(iz.x + hz.x);
        float n = tanhf(in.x + r * hn.x);
        o.x = (1.0f - z) * n + z * hv.x;
    }
    {
        float r = sigf(ir.y + hr.y), z = sigf(iz.y + hz.y);
        float n = tanhf(in.y + r * hn.y);
        o.y = (1.0f - z) * n + z * hv.y;
    }
    {
        float r = sigf(ir.z + hr.z), z = sigf(iz.z + hz.z);
        float n = tanhf(in.z + r * hn.z);
        o.z = (1.0f - z) * n + z * hv.z;
    }
    {
        float r = sigf(ir.w + hr.w), z = sigf(iz.w + hz.w);
        float n = tanhf(in.w + r * hn.w);
        o.w = (1.0f - z) * n + z * hv.w;
    }
    H[c4] = o;
}

// ---------------- head: out = log_softmax(relu(h) @ W_lin^T + b_lin) --------
// one warp per node, shuffle reduction over HID=256.
__global__ void head_kernel(const float* __restrict__ h,
                            const float* __restrict__ W_lin,
                            const float* __restrict__ b_lin,
                            float* __restrict__ out, int N)
{
    const int gt   = blockIdx.x * blockDim.x + threadIdx.x;
    const int node = gt >> 5;
    const int lane = gt & 31;
    if (node >= N) return;

    const float4* hr = (const float4*)(h + (size_t)node * HID);
    const float4* w0 = (const float4*)(W_lin);
    const float4* w1 = (const float4*)(W_lin + HID);

    float a0 = 0.0f, a1 = 0.0f;
#pragma unroll
    for (int it = 0; it < 2; it++) {
        const int i = lane + it * 32;      // 0..63 float4 slots
        float4 v  = hr[i];
        v.x = fmaxf(v.x, 0.f); v.y = fmaxf(v.y, 0.f);
        v.z = fmaxf(v.z, 0.f); v.w = fmaxf(v.w, 0.f);
        float4 x0 = w0[i], x1 = w1[i];
        a0 += v.x * x0.x + v.y * x0.y + v.z * x0.z + v.w * x0.w;
        a1 += v.x * x1.x + v.y * x1.y + v.z * x1.z + v.w * x1.w;
    }
#pragma unroll
    for (int off = 16; off > 0; off >>= 1) {
        a0 += __shfl_down_sync(0xffffffffu, a0, off);
        a1 += __shfl_down_sync(0xffffffffu, a1, off);
    }
    if (lane == 0) {
        float o0 = a0 + b_lin[0];
        float o1 = a1 + b_lin[1];
        float mx = fmaxf(o0, o1);
        float lse = mx + logf(expf(o0 - mx) + expf(o1 - mx));
        out[(size_t)node * 2 + 0] = o0 - lse;
        out[(size_t)node * 2 + 1] = o1 - lse;
    }
}

// ---------------- launch -----------------------------------------------------
extern "C" void kernel_launch(void* const* d_in, const int* in_sizes, int n_in,
                              void* d_out, int out_size)
{
    const float* x        = (const float*)d_in[0];
    const int*   ei       = (const int*)  d_in[1];
    // d_in[2] = batch (unused)
    const float* W_reduce = (const float*)d_in[3];
    const float* b_reduce = (const float*)d_in[4];
    const float* W_ggc    = (const float*)d_in[5];
    const float* W_ih     = (const float*)d_in[6];
    const float* W_hh     = (const float*)d_in[7];
    const float* b_ih     = (const float*)d_in[8];
    const float* b_hh     = (const float*)d_in[9];
    const float* W_lin    = (const float*)d_in[10];
    const float* b_lin    = (const float*)d_in[11];
    float* out = (float*)d_out;

    float *h, *m, *agg, *gi, *gh;
    cudaGetSymbolAddress((void**)&h,   g_h);
    cudaGetSymbolAddress((void**)&m,   g_m);
    cudaGetSymbolAddress((void**)&agg, g_agg);
    cudaGetSymbolAddress((void**)&gi,  g_gi);
    cudaGetSymbolAddress((void**)&gh,  g_gh);

    const int MB = (N_NODES + 127) / 128;   // 391

    // h = x @ W_reduce^T + b_reduce
    sgemm_kernel<true><<<dim3(HID / 128, MB), 256>>>(
        x, W_reduce, b_reduce, h, N_NODES, HID, ANNOT);

    for (int t = 0; t < N_STEPS; t++) {
        // m = h @ W_ggc[t]
        sgemm_kernel<false><<<dim3(HID / 128, MB), 256>>>(
            h, W_ggc + (size_t)t * HID * HID, nullptr, m, N_NODES, HID, HID);

        cudaMemsetAsync(agg, 0, (size_t)N_NODES * HID * sizeof(float));

        scatter_kernel<<<(N_EDGES * (HID / 4) + 255) / 256, 256>>>(m, ei, agg, N_EDGES);

        // gi = agg @ W_ih^T + b_ih ; gh = h @ W_hh^T + b_hh
        sgemm_kernel<true><<<dim3(3 * HID / 128, MB), 256>>>(
            agg, W_ih, b_ih, gi, N_NODES, 3 * HID, HID);
        sgemm_kernel<true><<<dim3(3 * HID / 128, MB), 256>>>(
            h, W_hh, b_hh, gh, N_NODES, 3 * HID, HID);

        gru_kernel<<<(N_NODES * (HID / 4) + 255) / 256, 256>>>(gi, gh, h, N_NODES);
    }

    head_kernel<<<(N_NODES * 32 + 255) / 256, 256>>>(h, W_lin, b_lin, out, N_NODES);
}

// round 2
// speedup vs baseline: 1.5807x; 1.5807x over previous
#include <cuda_runtime.h>
#include <cuda_bf16.h>
#include <math.h>

#define N_NODES 50000
#define N_EDGES 300000
#define ANNOT   200
#define HID     256
#define N_STEPS 8

// ---------------- scratch (static device globals; no runtime alloc) ----------
__device__ float g_h  [N_NODES * HID];
__device__ float g_m  [N_NODES * HID];
__device__ float g_agg[N_NODES * HID];
__device__ float g_gi [N_NODES * 3 * HID];
__device__ float g_gh [N_NODES * 3 * HID];

// ---------------- bf16-split tensor-core GEMM --------------------------------
// BT=true : C[M,N] = A[M,K] @ B[N,K]^T + bias   (B row-major [N,K])
// BT=false: C[M,N] = A[M,K] @ B[K,N]   + bias   (B row-major [K,N])
// Precision: x = hi + lo (two bf16); C = Ah*Bh + Ah*Bl + Al*Bh  (err ~2^-16)
// Requires: N % 128 == 0, K % 4 == 0. M guarded.
#define BM 128
#define BN 128
#define BK 32
#define SA 36   // padded k-stride (bf16 elems): 72B rows, 8B-aligned

__device__ __forceinline__ void mma_bf16(float* c, const unsigned* a, const unsigned* b)
{
    asm volatile(
        "mma.sync.aligned.m16n8k16.row.col.f32.bf16.bf16.f32 "
        "{%0,%1,%2,%3}, {%4,%5,%6,%7}, {%8,%9}, {%0,%1,%2,%3};\n"
        : "+f"(c[0]), "+f"(c[1]), "+f"(c[2]), "+f"(c[3])
        : "r"(a[0]), "r"(a[1]), "r"(a[2]), "r"(a[3]), "r"(b[0]), "r"(b[1]));
}

__device__ __forceinline__ void split_store(__nv_bfloat16* sh, __nv_bfloat16* sl,
                                            int off, float4 v)
{
    __nv_bfloat16 h0 = __float2bfloat16(v.x);
    __nv_bfloat16 h1 = __float2bfloat16(v.y);
    __nv_bfloat16 h2 = __float2bfloat16(v.z);
    __nv_bfloat16 h3 = __float2bfloat16(v.w);
    __nv_bfloat16 l0 = __float2bfloat16(v.x - __bfloat162float(h0));
    __nv_bfloat16 l1 = __float2bfloat16(v.y - __bfloat162float(h1));
    __nv_bfloat16 l2 = __float2bfloat16(v.z - __bfloat162float(h2));
    __nv_bfloat16 l3 = __float2bfloat16(v.w - __bfloat162float(h3));
    *(__nv_bfloat162*)(sh + off)     = __nv_bfloat162(h0, h1);
    *(__nv_bfloat162*)(sh + off + 2) = __nv_bfloat162(h2, h3);
    *(__nv_bfloat162*)(sl + off)     = __nv_bfloat162(l0, l1);
    *(__nv_bfloat162*)(sl + off + 2) = __nv_bfloat162(l2, l3);
}

template <bool BT>
__global__ void __launch_bounds__(256)
mma_gemm(const float* __restrict__ A, const float* __restrict__ B,
         const float* __restrict__ bias, float* __restrict__ C,
         int M, int N, int K)
{
    __shared__ __nv_bfloat16 Ah[BM * SA], Al[BM * SA];
    __shared__ __nv_bfloat16 Bh[BN * SA], Bl[BN * SA];

    const int tid  = threadIdx.x;
    const int lane = tid & 31;
    const int warp = tid >> 5;
    const int wm   = warp & 3;          // 4 warps along M (32 rows each)
    const int wn   = warp >> 2;         // 2 warps along N (64 cols each)
    const int row0 = blockIdx.y * BM;
    const int col0 = blockIdx.x * BN;
    const int g    = lane >> 2;         // 0..7
    const int tq   = lane & 3;          // 0..3

    float acc[2][8][4];
#pragma unroll
    for (int mi = 0; mi < 2; mi++)
#pragma unroll
        for (int ni = 0; ni < 8; ni++)
#pragma unroll
            for (int j = 0; j < 4; j++) acc[mi][ni][j] = 0.0f;

    for (int k0 = 0; k0 < K; k0 += BK) {
        // ---- load + split A tile: Ah/Al[row][k], K-contiguous ----
#pragma unroll
        for (int i = 0; i < 4; i++) {
            const int idx = i * 256 + tid;
            const int r   = idx >> 3;          // 0..127
            const int kq  = (idx & 7) * 4;     // 0..28
            const int ar  = row0 + r;
            const int kk  = k0 + kq;
            float4 v = make_float4(0.f, 0.f, 0.f, 0.f);
            if (ar < M && kk + 4 <= K)
                v = *(const float4*)(A + (size_t)ar * K + kk);
            split_store(Ah, Al, r * SA + kq, v);
        }
        // ---- load + split B tile into Bh/Bl[n][k] ----
        if (BT) {
#pragma unroll
            for (int i = 0; i < 4; i++) {
                const int idx = i * 256 + tid;
                const int r   = idx >> 3;
                const int kq  = (idx & 7) * 4;
                const int kk  = k0 + kq;
                float4 v = make_float4(0.f, 0.f, 0.f, 0.f);
                if (kk + 4 <= K)
                    v = *(const float4*)(B + (size_t)(col0 + r) * K + kk);
                split_store(Bh, Bl, r * SA + kq, v);
            }
        } else {
#pragma unroll
            for (int i = 0; i < 4; i++) {
                const int idx = i * 256 + tid;
                const int kr  = idx >> 5;          // 0..31
                const int nq  = (idx & 31) * 4;    // 0..124
                float4 v = make_float4(0.f, 0.f, 0.f, 0.f);
                if (k0 + kr < K)
                    v = *(const float4*)(B + (size_t)(k0 + kr) * N + col0 + nq);
                const float vv[4] = {v.x, v.y, v.z, v.w};
#pragma unroll
                for (int j = 0; j < 4; j++) {
                    __nv_bfloat16 h = __float2bfloat16(vv[j]);
                    __nv_bfloat16 l = __float2bfloat16(vv[j] - __bfloat162float(h));
                    Bh[(nq + j) * SA + kr] = h;
                    Bl[(nq + j) * SA + kr] = l;
                }
            }
        }
        __syncthreads();

        // ---- compute: 2 k16-steps ----
#pragma unroll
        for (int ks = 0; ks < 2; ks++) {
            const int kb = ks * 16 + tq * 2;
            unsigned aH[2][4], aL[2][4], bH[8][2], bL[8][2];
#pragma unroll
            for (int mi = 0; mi < 2; mi++) {
                const int r = wm * 32 + mi * 16 + g;
                aH[mi][0] = *(const unsigned*)&Ah[r * SA + kb];
                aH[mi][1] = *(const unsigned*)&Ah[(r + 8) * SA + kb];
                aH[mi][2] = *(const unsigned*)&Ah[r * SA + kb + 8];
                aH[mi][3] = *(const unsigned*)&Ah[(r + 8) * SA + kb + 8];
                aL[mi][0] = *(const unsigned*)&Al[r * SA + kb];
                aL[mi][1] = *(const unsigned*)&Al[(r + 8) * SA + kb];
                aL[mi][2] = *(const unsigned*)&Al[r * SA + kb + 8];
                aL[mi][3] = *(const unsigned*)&Al[(r + 8) * SA + kb + 8];
            }
#pragma unroll
            for (int ni = 0; ni < 8; ni++) {
                const int c = wn * 64 + ni * 8 + g;
                bH[ni][0] = *(const unsigned*)&Bh[c * SA + kb];
                bH[ni][1] = *(const unsigned*)&Bh[c * SA + kb + 8];
                bL[ni][0] = *(const unsigned*)&Bl[c * SA + kb];
                bL[ni][1] = *(const unsigned*)&Bl[c * SA + kb + 8];
            }
#pragma unroll
            for (int mi = 0; mi < 2; mi++)
#pragma unroll
                for (int ni = 0; ni < 8; ni++) {
                    mma_bf16(acc[mi][ni], aH[mi], bH[ni]);
                    mma_bf16(acc[mi][ni], aH[mi], bL[ni]);
                    mma_bf16(acc[mi][ni], aL[mi], bH[ni]);
                }
        }
        __syncthreads();
    }

    // ---- epilogue ----
#pragma unroll
    for (int mi = 0; mi < 2; mi++) {
        const int r = row0 + wm * 32 + mi * 16 + g;
#pragma unroll
        for (int ni = 0; ni < 8; ni++) {
            const int c = col0 + wn * 64 + ni * 8 + tq * 2;
            float b0 = 0.f, b1 = 0.f;
            if (bias) { b0 = bias[c]; b1 = bias[c + 1]; }
            if (r < M) {
                float2 v = make_float2(acc[mi][ni][0] + b0, acc[mi][ni][1] + b1);
                *(float2*)(C + (size_t)r * N + c) = v;
            }
            if (r + 8 < M) {
                float2 v = make_float2(acc[mi][ni][2] + b0, acc[mi][ni][3] + b1);
                *(float2*)(C + (size_t)(r + 8) * N + c) = v;
            }
        }
    }
}

// ---------------- scatter-add: agg[dst[e]] += m[src[e]] ---------------------
__global__ void scatter_kernel(const float* __restrict__ m,
                               const int* __restrict__ ei,
                               float* __restrict__ agg, int E)
{
    const int idx = blockIdx.x * blockDim.x + threadIdx.x;
    if (idx >= E * (HID / 4)) return;
    const int e  = idx >> 6;
    const int c4 = idx & 63;
    const int s = ei[e];
    const int d = ei[E + e];
    float4 v = *(const float4*)(m + (size_t)s * HID + c4 * 4);
    float* o = agg + (size_t)d * HID + c4 * 4;
    atomicAdd(o + 0, v.x);
    atomicAdd(o + 1, v.y);
    atomicAdd(o + 2, v.z);
    atomicAdd(o + 3, v.w);
}

// ---------------- fused GRU gates (in-place update of h) ---------------------
__device__ __forceinline__ float sigf(float x) { return 1.0f / (1.0f + __expf(-x)); }

__global__ void gru_kernel(const float* __restrict__ gi,
                           const float* __restrict__ gh,
                           float* __restrict__ h, int N)
{
    const int idx = blockIdx.x * blockDim.x + threadIdx.x;
    if (idx >= N * (HID / 4)) return;
    const int row = idx >> 6;
    const int c4  = idx & 63;
    const float4* GI = (const float4*)(gi + (size_t)row * 3 * HID);
    const float4* GH = (const float4*)(gh + (size_t)row * 3 * HID);
    float4 ir = GI[c4], iz = GI[64 + c4], in = GI[128 + c4];
    float4 hr = GH[c4], hz = GH[64 + c4], hn = GH[128 + c4];
    float4* H = (float4*)(h + (size_t)row * HID);
    float4 hv = H[c4];

    float4 o;
    { float r = sigf(ir.x + hr.x), z = sigf(iz.x + hz.x);
      float n = tanhf(in.x + r * hn.x); o.x = (1.0f - z) * n + z * hv.x; }
    { float r = sigf(ir.y + hr.y), z = sigf(iz.y + hz.y);
      float n = tanhf(in.y + r * hn.y); o.y = (1.0f - z) * n + z * hv.y; }
    { float r = sigf(ir.z + hr.z), z = sigf(iz.z + hz.z);
      float n = tanhf(in.z + r * hn.z); o.z = (1.0f - z) * n + z * hv.z; }
    { float r = sigf(ir.w + hr.w), z = sigf(iz.w + hz.w);
      float n = tanhf(in.w + r * hn.w); o.w = (1.0f - z) * n + z * hv.w; }
    H[c4] = o;
}

// ---------------- head: out = log_softmax(relu(h) @ W_lin^T + b_lin) --------
__global__ void head_kernel(const float* __restrict__ h,
                            const float* __restrict__ W_lin,
                            const float* __restrict__ b_lin,
                            float* __restrict__ out, int N)
{
    const int gt   = blockIdx.x * blockDim.x + threadIdx.x;
    const int node = gt >> 5;
    const int lane = gt & 31;
    if (node >= N) return;

    const float4* hr = (const float4*)(h + (size_t)node * HID);
    const float4* w0 = (const float4*)(W_lin);
    const float4* w1 = (const float4*)(W_lin + HID);

    float a0 = 0.0f, a1 = 0.0f;
#pragma unroll
    for (int it = 0; it < 2; it++) {
        const int i = lane + it * 32;
        float4 v = hr[i];
        v.x = fmaxf(v.x, 0.f); v.y = fmaxf(v.y, 0.f);
        v.z = fmaxf(v.z, 0.f); v.w = fmaxf(v.w, 0.f);
        float4 x0 = w0[i], x1 = w1[i];
        a0 += v.x * x0.x + v.y * x0.y + v.z * x0.z + v.w * x0.w;
        a1 += v.x * x1.x + v.y * x1.y + v.z * x1.z + v.w * x1.w;
    }
#pragma unroll
    for (int off = 16; off > 0; off >>= 1) {
        a0 += __shfl_down_sync(0xffffffffu, a0, off);
        a1 += __shfl_down_sync(0xffffffffu, a1, off);
    }
    if (lane == 0) {
        float o0 = a0 + b_lin[0];
        float o1 = a1 + b_lin[1];
        float mx = fmaxf(o0, o1);
        float lse = mx + logf(expf(o0 - mx) + expf(o1 - mx));
        out[(size_t)node * 2 + 0] = o0 - lse;
        out[(size_t)node * 2 + 1] = o1 - lse;
    }
}

// ---------------- launch -----------------------------------------------------
extern "C" void kernel_launch(void* const* d_in, const int* in_sizes, int n_in,
                              void* d_out, int out_size)
{
    const float* x        = (const float*)d_in[0];
    const int*   ei       = (const int*)  d_in[1];
    const float* W_reduce = (const float*)d_in[3];
    const float* b_reduce = (const float*)d_in[4];
    const float* W_ggc    = (const float*)d_in[5];
    const float* W_ih     = (const float*)d_in[6];
    const float* W_hh     = (const float*)d_in[7];
    const float* b_ih     = (const float*)d_in[8];
    const float* b_hh     = (const float*)d_in[9];
    const float* W_lin    = (const float*)d_in[10];
    const float* b_lin    = (const float*)d_in[11];
    float* out = (float*)d_out;

    float *h, *m, *agg, *gi, *gh;
    cudaGetSymbolAddress((void**)&h,   g_h);
    cudaGetSymbolAddress((void**)&m,   g_m);
    cudaGetSymbolAddress((void**)&agg, g_agg);
    cudaGetSymbolAddress((void**)&gi,  g_gi);
    cudaGetSymbolAddress((void**)&gh,  g_gh);

    const int MB = (N_NODES + BM - 1) / BM;   // 391

    // h = x @ W_reduce^T + b_reduce
    mma_gemm<true><<<dim3(HID / BN, MB), 256>>>(
        x, W_reduce, b_reduce, h, N_NODES, HID, ANNOT);

    for (int t = 0; t < N_STEPS; t++) {
        // m = h @ W_ggc[t]
        mma_gemm<false><<<dim3(HID / BN, MB), 256>>>(
            h, W_ggc + (size_t)t * HID * HID, nullptr, m, N_NODES, HID, HID);

        cudaMemsetAsync(agg, 0, (size_t)N_NODES * HID * sizeof(float));

        scatter_kernel<<<(N_EDGES * (HID / 4) + 255) / 256, 256>>>(m, ei, agg, N_EDGES);

        // gi = agg @ W_ih^T + b_ih ; gh = h @ W_hh^T + b_hh
        mma_gemm<true><<<dim3(3 * HID / BN, MB), 256>>>(
            agg, W_ih, b_ih, gi, N_NODES, 3 * HID, HID);
        mma_gemm<true><<<dim3(3 * HID / BN, MB), 256>>>(
            h, W_hh, b_hh, gh, N_NODES, 3 * HID, HID);

        gru_kernel<<<(N_NODES * (HID / 4) + 255) / 256, 256>>>(gi, gh, h, N_NODES);
    }

    head_kernel<<<(N_NODES * 32 + 255) / 256, 256>>>(h, W_lin, b_lin, out, N_NODES);
}

// round 5
// speedup vs baseline: 2.8842x; 1.8246x over previous
#include <cuda_runtime.h>
#include <cuda_bf16.h>
#include <math.h>
#include <stdint.h>

#define NN      50048      // padded node count (391 * 128)
#define NREAL   50000
#define NE      300000
#define KD      256        // padded K dim
#define HID     256
#define NSTEP   8

// ---------------- scratch (static device globals; no runtime alloc) ----------
__device__ float g_h  [NN * HID];
__device__ float g_mgh[NN * 1024];        // [m(256) | gh(768)]
__device__ float g_gi [NN * 768];
__device__ __nv_bfloat16 g_hH[NN * KD],  g_hL[NN * KD];
__device__ __nv_bfloat16 g_xH[NN * KD],  g_xL[NN * KD];
__device__ __nv_bfloat16 g_aggH[NN * KD], g_aggL[NN * KD];
__device__ __nv_bfloat16 g_WcombH[NSTEP * 1024 * KD], g_WcombL[NSTEP * 1024 * KD];
__device__ __nv_bfloat16 g_WihH[768 * KD], g_WihL[768 * KD];
__device__ __nv_bfloat16 g_WredH[256 * KD], g_WredL[256 * KD];
__device__ float g_bcomb[1024];
__device__ int g_cnt[NN], g_rowptr[NN + 1], g_cur[NN], g_eidx[NE];

// ---------------- mma.sync bf16-split GEMM -----------------------------------
// C[M,N] = A@B^T + bias.  A planes [M][256] bf16 hi/lo, B planes [N][256]
// bf16 hi/lo, K-contiguous.  M = NN (padded), N % 128 == 0, K = 256.
// Split product: C = Ah*Bh + Ah*Bl + Al*Bh.
#define BK    32
#define SA    40                       // row stride in bf16 elems (80B, 16B-aligned)
#define PLANEB (128 * SA * 2)          // 10240 B per plane
#define STAGEB (4 * PLANEB)            // 40960 B per stage
#define GSMEM  (2 * STAGEB)            // 81920 B

__device__ __forceinline__ void mma_bf16(float* c, const unsigned* a, const unsigned* b)
{
    asm volatile(
        "mma.sync.aligned.m16n8k16.row.col.f32.bf16.bf16.f32 "
        "{%0,%1,%2,%3}, {%4,%5,%6,%7}, {%8,%9}, {%0,%1,%2,%3};\n"
        : "+f"(c[0]), "+f"(c[1]), "+f"(c[2]), "+f"(c[3])
        : "r"(a[0]), "r"(a[1]), "r"(a[2]), "r"(a[3]), "r"(b[0]), "r"(b[1]));
}

__global__ void __launch_bounds__(256, 2)
gemm_mma(const __nv_bfloat16* __restrict__ AH, const __nv_bfloat16* __restrict__ AL,
         const __nv_bfloat16* __restrict__ BH, const __nv_bfloat16* __restrict__ BL,
         const float* __restrict__ bias, float* __restrict__ C, int ldc)
{
    extern __shared__ char sm[];
    const int tid  = threadIdx.x;
    const int lane = tid & 31;
    const int warp = tid >> 5;
    const int wm   = warp & 3;          // 4 warps x 32 rows
    const int wn   = warp >> 2;         // 2 warps x 64 cols
    const int row0 = blockIdx.y * 128;
    const int col0 = blockIdx.x * 128;
    const int g    = lane >> 2;
    const int tq   = lane & 3;

    // cp.async one BK-chunk into stage st
    auto copy_stage = [&](int st, int kc) {
        const int k0 = kc * BK;
        char* dst0 = sm + st * STAGEB;
#pragma unroll
        for (int i = 0; i < 8; i++) {
            const int idx = i * 256 + tid;        // 0..2047 16B chunks
            const int p = idx >> 9;               // plane 0..3
            const int r = (idx >> 2) & 127;       // row in tile
            const int j = idx & 3;                // 16B chunk in row
            const __nv_bfloat16* gp = (p == 0) ? AH : (p == 1) ? AL : (p == 2) ? BH : BL;
            const int grow = ((p < 2) ? row0 : col0) + r;
            const void* src = gp + (size_t)grow * KD + k0 + j * 8;
            char* dst = dst0 + p * PLANEB + r * (SA * 2) + j * 16;
            asm volatile("cp.async.cg.shared.global [%0], [%1], 16;"
                         :: "l"((uint64_t)__cvta_generic_to_shared(dst)), "l"(src)
                         : "memory");
        }
        asm volatile("cp.async.commit_group;" ::: "memory");
    };

    float acc[2][8][4];
#pragma unroll
    for (int mi = 0; mi < 2; mi++)
#pragma unroll
        for (int ni = 0; ni < 8; ni++)
#pragma unroll
            for (int j = 0; j < 4; j++) acc[mi][ni][j] = 0.0f;

    copy_stage(0, 0);

    const int NCHUNK = KD / BK;   // 8
    for (int c = 0; c < NCHUNK; c++) {
        const int st = c & 1;
        if (c + 1 < NCHUNK) {
            copy_stage(st ^ 1, c + 1);
            asm volatile("cp.async.wait_group 1;" ::: "memory");
        } else {
            asm volatile("cp.async.wait_group 0;" ::: "memory");
        }
        __syncthreads();

        const __nv_bfloat16* Ah = (const __nv_bfloat16*)(sm + st * STAGEB + 0 * PLANEB);
        const __nv_bfloat16* Al = (const __nv_bfloat16*)(sm + st * STAGEB + 1 * PLANEB);
        const __nv_bfloat16* Bh = (const __nv_bfloat16*)(sm + st * STAGEB + 2 * PLANEB);
        const __nv_bfloat16* Bl = (const __nv_bfloat16*)(sm + st * STAGEB + 3 * PLANEB);

#pragma unroll
        for (int ks = 0; ks < 2; ks++) {
            const int kb = ks * 16 + tq * 2;
            unsigned aH[2][4], aL[2][4];
#pragma unroll
            for (int mi = 0; mi < 2; mi++) {
                const int r = wm * 32 + mi * 16 + g;
                aH[mi][0] = *(const unsigned*)&Ah[r * SA + kb];
                aH[mi][1] = *(const unsigned*)&Ah[(r + 8) * SA + kb];
                aH[mi][2] = *(const unsigned*)&Ah[r * SA + kb + 8];
                aH[mi][3] = *(const unsigned*)&Ah[(r + 8) * SA + kb + 8];
                aL[mi][0] = *(const unsigned*)&Al[r * SA + kb];
                aL[mi][1] = *(const unsigned*)&Al[(r + 8) * SA + kb];
                aL[mi][2] = *(const unsigned*)&Al[r * SA + kb + 8];
                aL[mi][3] = *(const unsigned*)&Al[(r + 8) * SA + kb + 8];
            }
#pragma unroll
            for (int ni = 0; ni < 8; ni++) {
                const int col = wn * 64 + ni * 8 + g;
                unsigned bH[2], bL[2];
                bH[0] = *(const unsigned*)&Bh[col * SA + kb];
                bH[1] = *(const unsigned*)&Bh[col * SA + kb + 8];
                bL[0] = *(const unsigned*)&Bl[col * SA + kb];
                bL[1] = *(const unsigned*)&Bl[col * SA + kb + 8];
#pragma unroll
                for (int mi = 0; mi < 2; mi++) {
                    mma_bf16(acc[mi][ni], aH[mi], bH);
                    mma_bf16(acc[mi][ni], aH[mi], bL);
                    mma_bf16(acc[mi][ni], aL[mi], bH);
                }
            }
        }
        __syncthreads();
    }

    // ---- epilogue: direct stores (rows fully padded, no guards) ----
#pragma unroll
    for (int mi = 0; mi < 2; mi++) {
        const int r = row0 + wm * 32 + mi * 16 + g;
#pragma unroll
        for (int ni = 0; ni < 8; ni++) {
            const int cc = col0 + wn * 64 + ni * 8 + tq * 2;
            const float b0 = bias[cc], b1 = bias[cc + 1];
            *(float2*)(C + (size_t)r * ldc + cc) =
                make_float2(acc[mi][ni][0] + b0, acc[mi][ni][1] + b1);
            *(float2*)(C + (size_t)(r + 8) * ldc + cc) =
                make_float2(acc[mi][ni][2] + b0, acc[mi][ni][3] + b1);
        }
    }
}

// ---------------- split helpers ---------------------------------------------
__device__ __forceinline__ void split1(float v, __nv_bfloat16& h, __nv_bfloat16& l) {
    h = __float2bfloat16(v);
    l = __float2bfloat16(v - __bfloat162float(h));
}

// ---------------- prep kernels (every launch) --------------------------------
__global__ void prep_x(const float* __restrict__ x,
                       __nv_bfloat16* __restrict__ xh, __nv_bfloat16* __restrict__ xl) {
    const int idx = blockIdx.x * 256 + threadIdx.x;
    if (idx >= NN * KD) return;
    const int row = idx >> 8, col = idx & 255;
    const float v = (row < NREAL && col < 200) ? x[row * 200 + col] : 0.0f;
    split1(v, xh[idx], xl[idx]);
}
__global__ void prep_wred(const float* __restrict__ W,
                          __nv_bfloat16* __restrict__ wh, __nv_bfloat16* __restrict__ wl) {
    const int idx = blockIdx.x * 256 + threadIdx.x;
    if (idx >= 256 * KD) return;
    const int n = idx >> 8, k = idx & 255;
    const float v = (k < 200) ? W[n * 200 + k] : 0.0f;
    split1(v, wh[idx], wl[idx]);
}
__global__ void prep_wcomb(const float* __restrict__ Wggc, const float* __restrict__ Whh,
                           __nv_bfloat16* __restrict__ wh, __nv_bfloat16* __restrict__ wl) {
    const int idx = blockIdx.x * 256 + threadIdx.x;
    if (idx >= NSTEP * 1024 * KD) return;
    const int t = idx >> 18;
    const int rem = idx & 0x3FFFF;
    const int n = rem >> 8, k = rem & 255;
    const float v = (n < 256) ? Wggc[t * 65536 + k * 256 + n]   // W_ggc[t][k][n] (A@B, no T)
                              : Whh[(n - 256) * 256 + k];        // W_hh[n'][k]   (A@B^T)
    split1(v, wh[idx], wl[idx]);
}
__global__ void prep_wih(const float* __restrict__ W,
                         __nv_bfloat16* __restrict__ wh, __nv_bfloat16* __restrict__ wl) {
    const int idx = blockIdx.x * 256 + threadIdx.x;
    if (idx >= 768 * KD) return;
    split1(W[idx], wh[idx], wl[idx]);
}
__global__ void prep_bcomb(const float* __restrict__ bhh, float* __restrict__ bc) {
    const int idx = blockIdx.x * 256 + threadIdx.x;
    if (idx >= 1024) return;
    bc[idx] = (idx < 256) ? 0.0f : bhh[idx - 256];
}
__global__ void split_h(const float* __restrict__ h,
                        __nv_bfloat16* __restrict__ hh, __nv_bfloat16* __restrict__ hl) {
    const int idx = blockIdx.x * 256 + threadIdx.x;
    if (idx >= NN * HID) return;
    split1(h[idx], hh[idx], hl[idx]);
}

// ---------------- CSR build --------------------------------------------------
__global__ void hist_kernel(const int* __restrict__ ei, int* __restrict__ cnt) {
    const int e = blockIdx.x * 256 + threadIdx.x;
    if (e >= NE) return;
    atomicAdd(&cnt[ei[NE + e]], 1);
}
__global__ void scan_kernel(const int* __restrict__ cnt, int* __restrict__ rowptr) {
    __shared__ int s[1024];
    __shared__ int carryS;
    const int tid = threadIdx.x;
    if (tid == 0) { carryS = 0; rowptr[0] = 0; }
    __syncthreads();
    for (int base = 0; base < NN; base += 1024) {
        const int idx = base + tid;
        int v = (idx < NN) ? cnt[idx] : 0;
        s[tid] = v;
        __syncthreads();
        for (int off = 1; off < 1024; off <<= 1) {
            int t = (tid >= off) ? s[tid - off] : 0;
            __syncthreads();
            s[tid] += t;
            __syncthreads();
        }
        const int carry = carryS;
        if (idx < NN) rowptr[idx + 1] = carry + s[tid];
        __syncthreads();
        if (tid == 1023) carryS = carry + s[1023];
        __syncthreads();
    }
}
__global__ void copycur_kernel(const int* __restrict__ rowptr, int* __restrict__ cur) {
    const int i = blockIdx.x * 256 + threadIdx.x;
    if (i < NN) cur[i] = rowptr[i];
}
__global__ void fill_kernel(const int* __restrict__ ei, int* __restrict__ cur,
                            int* __restrict__ eidx) {
    const int e = blockIdx.x * 256 + threadIdx.x;
    if (e >= NE) return;
    const int pos = atomicAdd(&cur[ei[NE + e]], 1);
    eidx[pos] = ei[e];
}

// ---------------- aggregation: warp per dst node -> bf16 planes --------------
__global__ void agg_kernel(const float* __restrict__ mgh,
                           const int* __restrict__ rowptr, const int* __restrict__ eidx,
                           __nv_bfloat16* __restrict__ aggH, __nv_bfloat16* __restrict__ aggL)
{
    const int w = (blockIdx.x * blockDim.x + threadIdx.x) >> 5;
    const int lane = threadIdx.x & 31;
    if (w >= NN) return;
    const int beg = rowptr[w], end = rowptr[w + 1];
    float4 a0 = make_float4(0, 0, 0, 0), a1 = make_float4(0, 0, 0, 0);
    for (int i = beg; i < end; i++) {
        const int s = eidx[i];
        const float4* mr = (const float4*)(mgh + (size_t)s * 1024);
        const float4 v0 = mr[lane * 2], v1 = mr[lane * 2 + 1];
        a0.x += v0.x; a0.y += v0.y; a0.z += v0.z; a0.w += v0.w;
        a1.x += v1.x; a1.y += v1.y; a1.z += v1.z; a1.w += v1.w;
    }
    const float vals[8] = {a0.x, a0.y, a0.z, a0.w, a1.x, a1.y, a1.z, a1.w};
    unsigned hb[4], lb[4];
#pragma unroll
    for (int q = 0; q < 4; q++) {
        __nv_bfloat16 h0, l0, h1, l1;
        split1(vals[2 * q], h0, l0);
        split1(vals[2 * q + 1], h1, l1);
        __nv_bfloat162 ph(h0, h1), pl(l0, l1);
        hb[q] = *(unsigned*)&ph;
        lb[q] = *(unsigned*)&pl;
    }
    *(uint4*)(aggH + (size_t)w * 256 + lane * 8) = make_uint4(hb[0], hb[1], hb[2], hb[3]);
    *(uint4*)(aggL + (size_t)w * 256 + lane * 8) = make_uint4(lb[0], lb[1], lb[2], lb[3]);
}

// ---------------- fused GRU: h' = gru(gi, gh, h); also emits h planes --------
__device__ __forceinline__ float sigf(float x) { return 1.0f / (1.0f + __expf(-x)); }

__global__ void gru_kernel(const float* __restrict__ gi_, const float* __restrict__ mgh,
                           float* __restrict__ h,
                           __nv_bfloat16* __restrict__ hh, __nv_bfloat16* __restrict__ hl)
{
    const int idx = blockIdx.x * blockDim.x + threadIdx.x;
    if (idx >= NN * 64) return;
    const int row = idx >> 6, c = (idx & 63) * 4;
    const float* gi = gi_ + (size_t)row * 768;
    const float* gh = mgh + (size_t)row * 1024 + 256;
    const float4 ir = *(const float4*)(gi + c);
    const float4 iz = *(const float4*)(gi + 256 + c);
    const float4 in = *(const float4*)(gi + 512 + c);
    const float4 hr = *(const float4*)(gh + c);
    const float4 hz = *(const float4*)(gh + 256 + c);
    const float4 hn = *(const float4*)(gh + 512 + c);
    float4* H = (float4*)(h + (size_t)row * 256 + c);
    const float4 hv = *H;

    float4 o;
    { float r = sigf(ir.x + hr.x), z = sigf(iz.x + hz.x);
      float n = tanhf(in.x + r * hn.x); o.x = (1.0f - z) * n + z * hv.x; }
    { float r = sigf(ir.y + hr.y), z = sigf(iz.y + hz.y);
      float n = tanhf(in.y + r * hn.y); o.y = (1.0f - z) * n + z * hv.y; }
    { float r = sigf(ir.z + hr.z), z = sigf(iz.z + hz.z);
      float n = tanhf(in.z + r * hn.z); o.z = (1.0f - z) * n + z * hv.z; }
    { float r = sigf(ir.w + hr.w), z = sigf(iz.w + hz.w);
      float n = tanhf(in.w + r * hn.w); o.w = (1.0f - z) * n + z * hv.w; }
    *H = o;

    __nv_bfloat16 h0, l0, h1, l1, h2, l2, h3, l3;
    split1(o.x, h0, l0); split1(o.y, h1, l1);
    split1(o.z, h2, l2); split1(o.w, h3, l3);
    __nv_bfloat162 p01(h0, h1), p23(h2, h3), q01(l0, l1), q23(l2, l3);
    *(__nv_bfloat162*)(hh + (size_t)row * 256 + c)     = p01;
    *(__nv_bfloat162*)(hh + (size_t)row * 256 + c + 2) = p23;
    *(__nv_bfloat162*)(hl + (size_t)row * 256 + c)     = q01;
    *(__nv_bfloat162*)(hl + (size_t)row * 256 + c + 2) = q23;
}

// ---------------- head -------------------------------------------------------
__global__ void head_kernel(const float* __restrict__ h,
                            const float* __restrict__ W_lin,
                            const float* __restrict__ b_lin,
                            float* __restrict__ out, int N)
{
    const int gt = blockIdx.x * blockDim.x + threadIdx.x;
    const int node = gt >> 5;
    const int lane = gt & 31;
    if (node >= N) return;
    const float4* hr = (const float4*)(h + (size_t)node * HID);
    const float4* w0 = (const float4*)(W_lin);
    const float4* w1 = (const float4*)(W_lin + HID);
    float a0 = 0.0f, a1 = 0.0f;
#pragma unroll
    for (int it = 0; it < 2; it++) {
        const int i = lane + it * 32;
        float4 v = hr[i];
        v.x = fmaxf(v.x, 0.f); v.y = fmaxf(v.y, 0.f);
        v.z = fmaxf(v.z, 0.f); v.w = fmaxf(v.w, 0.f);
        const float4 x0 = w0[i], x1 = w1[i];
        a0 += v.x * x0.x + v.y * x0.y + v.z * x0.z + v.w * x0.w;
        a1 += v.x * x1.x + v.y * x1.y + v.z * x1.z + v.w * x1.w;
    }
#pragma unroll
    for (int off = 16; off > 0; off >>= 1) {
        a0 += __shfl_down_sync(0xffffffffu, a0, off);
        a1 += __shfl_down_sync(0xffffffffu, a1, off);
    }
    if (lane == 0) {
        const float o0 = a0 + b_lin[0];
        const float o1 = a1 + b_lin[1];
        const float mx = fmaxf(o0, o1);
        const float lse = mx + logf(expf(o0 - mx) + expf(o1 - mx));
        out[(size_t)node * 2 + 0] = o0 - lse;
        out[(size_t)node * 2 + 1] = o1 - lse;
    }
}

// ---------------- launch -----------------------------------------------------
extern "C" void kernel_launch(void* const* d_in, const int* in_sizes, int n_in,
                              void* d_out, int out_size)
{
    const float* x        = (const float*)d_in[0];
    const int*   ei       = (const int*)  d_in[1];
    const float* W_reduce = (const float*)d_in[3];
    const float* b_reduce = (const float*)d_in[4];
    const float* W_ggc    = (const float*)d_in[5];
    const float* W_ih     = (const float*)d_in[6];
    const float* W_hh     = (const float*)d_in[7];
    const float* b_ih     = (const float*)d_in[8];
    const float* b_hh     = (const float*)d_in[9];
    const float* W_lin    = (const float*)d_in[10];
    const float* b_lin    = (const float*)d_in[11];
    float* out = (float*)d_out;

    float *h, *mgh, *gi, *bcomb;
    __nv_bfloat16 *hH, *hL, *xH, *xL, *aggH, *aggL, *WcH, *WcL, *WiH, *WiL, *WrH, *WrL;
    int *cnt, *rowptr, *cur, *eidx;
    cudaGetSymbolAddress((void**)&h, g_h);
    cudaGetSymbolAddress((void**)&mgh, g_mgh);
    cudaGetSymbolAddress((void**)&gi, g_gi);
    cudaGetSymbolAddress((void**)&bcomb, g_bcomb);
    cudaGetSymbolAddress((void**)&hH, g_hH);
    cudaGetSymbolAddress((void**)&hL, g_hL);
    cudaGetSymbolAddress((void**)&xH, g_xH);
    cudaGetSymbolAddress((void**)&xL, g_xL);
    cudaGetSymbolAddress((void**)&aggH, g_aggH);
    cudaGetSymbolAddress((void**)&aggL, g_aggL);
    cudaGetSymbolAddress((void**)&WcH, g_WcombH);
    cudaGetSymbolAddress((void**)&WcL, g_WcombL);
    cudaGetSymbolAddress((void**)&WiH, g_WihH);
    cudaGetSymbolAddress((void**)&WiL, g_WihL);
    cudaGetSymbolAddress((void**)&WrH, g_WredH);
    cudaGetSymbolAddress((void**)&WrL, g_WredL);
    cudaGetSymbolAddress((void**)&cnt, g_cnt);
    cudaGetSymbolAddress((void**)&rowptr, g_rowptr);
    cudaGetSymbolAddress((void**)&cur, g_cur);
    cudaGetSymbolAddress((void**)&eidx, g_eidx);

    cudaFuncSetAttribute(gemm_mma, cudaFuncAttributeMaxDynamicSharedMemorySize, GSMEM);

    // ---- preprocessing ----
    prep_x<<<(NN * KD + 255) / 256, 256>>>(x, xH, xL);
    prep_wred<<<(256 * KD + 255) / 256, 256>>>(W_reduce, WrH, WrL);
    prep_wcomb<<<(NSTEP * 1024 * KD + 255) / 256, 256>>>(W_ggc, W_hh, WcH, WcL);
    prep_wih<<<(768 * KD + 255) / 256, 256>>>(W_ih, WiH, WiL);
    prep_bcomb<<<4, 256>>>(b_hh, bcomb);
    cudaMemsetAsync(cnt, 0, NN * sizeof(int));
    hist_kernel<<<(NE + 255) / 256, 256>>>(ei, cnt);
    scan_kernel<<<1, 1024>>>(cnt, rowptr);
    copycur_kernel<<<(NN + 255) / 256, 256>>>(rowptr, cur);
    fill_kernel<<<(NE + 255) / 256, 256>>>(ei, cur, eidx);

    const int MB = NN / 128;   // 391

    // h = x @ W_reduce^T + b_reduce
    gemm_mma<<<dim3(2, MB), 256, GSMEM>>>(xH, xL, WrH, WrL, b_reduce, h, 256);
    split_h<<<(NN * HID + 255) / 256, 256>>>(h, hH, hL);

    for (int t = 0; t < NSTEP; t++) {
        // [m | gh] = h @ [W_ggc[t] | W_hh]^T (+ [0 | b_hh])
        gemm_mma<<<dim3(8, MB), 256, GSMEM>>>(
            hH, hL, WcH + (size_t)t * 1024 * KD, WcL + (size_t)t * 1024 * KD,
            bcomb, mgh, 1024);
        // agg = segment_sum(m[src] -> dst)  (CSR gather, bf16 planes out)
        agg_kernel<<<(NN * 32 + 255) / 256, 256>>>(mgh, rowptr, eidx, aggH, aggL);
        // gi = agg @ W_ih^T + b_ih
        gemm_mma<<<dim3(6, MB), 256, GSMEM>>>(aggH, aggL, WiH, WiL, b_ih, gi, 768);
        // h = GRU(gi, gh, h) ; emit h planes
        gru_kernel<<<(NN * 64 + 255) / 256, 256>>>(gi, mgh, h, hH, hL);
    }

    head_kernel<<<(NREAL * 32 + 255) / 256, 256>>>(h, W_lin, b_lin, out, NREAL);
}

// round 6
// speedup vs baseline: 3.1501x; 1.0922x over previous
#include <cuda_runtime.h>
#include <cuda_bf16.h>
#include <math.h>
#include <stdint.h>

#define NN      50048      // padded node count (391 * 128)
#define NREAL   50000
#define NE      300000
#define KD      256        // padded K dim
#define HID     256
#define NSTEP   8

// ---------------- scratch (static device globals; no runtime alloc) ----------
__device__ float g_h  [NN * HID];
__device__ float g_gh [NN * 768];
__device__ float g_gi [NN * 768];
__device__ __nv_bfloat16 g_hH[NN * KD],  g_hL[NN * KD];
__device__ __nv_bfloat16 g_xH[NN * KD],  g_xL[NN * KD];
__device__ __nv_bfloat16 g_aggH[NN * KD], g_aggL[NN * KD];
__device__ __nv_bfloat16 g_WfusH[NSTEP * 768 * KD], g_WfusL[NSTEP * 768 * KD];
__device__ __nv_bfloat16 g_WhhH[768 * KD], g_WhhL[768 * KD];
__device__ __nv_bfloat16 g_WredH[256 * KD], g_WredL[256 * KD];
__device__ int g_cnt[NN], g_rowptr[NN + 1], g_cur[NN], g_eidx[NE];

// ---------------- mma.sync bf16-split GEMM -----------------------------------
// C[M,N] = A@B^T + bias.  A planes [M][256] hi/lo, B planes [N][256] hi/lo.
// Split product: C = Ah*Bh + Ah*Bl + Al*Bh.
#define BK    32
#define SA    40                       // row stride in bf16 elems (80B)
#define PLANEB (128 * SA * 2)          // 10240 B per plane
#define STAGEB (4 * PLANEB)            // 40960 B per stage
#define GSMEM  (2 * STAGEB)            // 81920 B

__device__ __forceinline__ void mma_bf16(float* c, const unsigned* a, const unsigned* b)
{
    asm volatile(
        "mma.sync.aligned.m16n8k16.row.col.f32.bf16.bf16.f32 "
        "{%0,%1,%2,%3}, {%4,%5,%6,%7}, {%8,%9}, {%0,%1,%2,%3};\n"
        : "+f"(c[0]), "+f"(c[1]), "+f"(c[2]), "+f"(c[3])
        : "r"(a[0]), "r"(a[1]), "r"(a[2]), "r"(a[3]), "r"(b[0]), "r"(b[1]));
}

__global__ void __launch_bounds__(256, 2)
gemm_mma(const __nv_bfloat16* __restrict__ AH, const __nv_bfloat16* __restrict__ AL,
         const __nv_bfloat16* __restrict__ BH, const __nv_bfloat16* __restrict__ BL,
         const float* __restrict__ bias, float* __restrict__ C, int ldc)
{
    extern __shared__ char sm[];
    const int tid  = threadIdx.x;
    const int lane = tid & 31;
    const int warp = tid >> 5;
    const int wm   = warp & 3;
    const int wn   = warp >> 2;
    const int row0 = blockIdx.y * 128;
    const int col0 = blockIdx.x * 128;
    const int g    = lane >> 2;
    const int tq   = lane & 3;

    auto copy_stage = [&](int st, int kc) {
        const int k0 = kc * BK;
        char* dst0 = sm + st * STAGEB;
#pragma unroll
        for (int i = 0; i < 8; i++) {
            const int idx = i * 256 + tid;
            const int p = idx >> 9;
            const int r = (idx >> 2) & 127;
            const int j = idx & 3;
            const __nv_bfloat16* gp = (p == 0) ? AH : (p == 1) ? AL : (p == 2) ? BH : BL;
            const int grow = ((p < 2) ? row0 : col0) + r;
            const void* src = gp + (size_t)grow * KD + k0 + j * 8;
            char* dst = dst0 + p * PLANEB + r * (SA * 2) + j * 16;
            asm volatile("cp.async.cg.shared.global [%0], [%1], 16;"
                         :: "l"((uint64_t)__cvta_generic_to_shared(dst)), "l"(src)
                         : "memory");
        }
        asm volatile("cp.async.commit_group;" ::: "memory");
    };

    float acc[2][8][4];
#pragma unroll
    for (int mi = 0; mi < 2; mi++)
#pragma unroll
        for (int ni = 0; ni < 8; ni++)
#pragma unroll
            for (int j = 0; j < 4; j++) acc[mi][ni][j] = 0.0f;

    copy_stage(0, 0);

    const int NCHUNK = KD / BK;
    for (int c = 0; c < NCHUNK; c++) {
        const int st = c & 1;
        if (c + 1 < NCHUNK) {
            copy_stage(st ^ 1, c + 1);
            asm volatile("cp.async.wait_group 1;" ::: "memory");
        } else {
            asm volatile("cp.async.wait_group 0;" ::: "memory");
        }
        __syncthreads();

        const __nv_bfloat16* Ah = (const __nv_bfloat16*)(sm + st * STAGEB + 0 * PLANEB);
        const __nv_bfloat16* Al = (const __nv_bfloat16*)(sm + st * STAGEB + 1 * PLANEB);
        const __nv_bfloat16* Bh = (const __nv_bfloat16*)(sm + st * STAGEB + 2 * PLANEB);
        const __nv_bfloat16* Bl = (const __nv_bfloat16*)(sm + st * STAGEB + 3 * PLANEB);

#pragma unroll
        for (int ks = 0; ks < 2; ks++) {
            const int kb = ks * 16 + tq * 2;
            unsigned aH[2][4], aL[2][4];
#pragma unroll
            for (int mi = 0; mi < 2; mi++) {
                const int r = wm * 32 + mi * 16 + g;
                aH[mi][0] = *(const unsigned*)&Ah[r * SA + kb];
                aH[mi][1] = *(const unsigned*)&Ah[(r + 8) * SA + kb];
                aH[mi][2] = *(const unsigned*)&Ah[r * SA + kb + 8];
                aH[mi][3] = *(const unsigned*)&Ah[(r + 8) * SA + kb + 8];
                aL[mi][0] = *(const unsigned*)&Al[r * SA + kb];
                aL[mi][1] = *(const unsigned*)&Al[(r + 8) * SA + kb];
                aL[mi][2] = *(const unsigned*)&Al[r * SA + kb + 8];
                aL[mi][3] = *(const unsigned*)&Al[(r + 8) * SA + kb + 8];
            }
#pragma unroll
            for (int ni = 0; ni < 8; ni++) {
                const int col = wn * 64 + ni * 8 + g;
                unsigned bH[2], bL[2];
                bH[0] = *(const unsigned*)&Bh[col * SA + kb];
                bH[1] = *(const unsigned*)&Bh[col * SA + kb + 8];
                bL[0] = *(const unsigned*)&Bl[col * SA + kb];
                bL[1] = *(const unsigned*)&Bl[col * SA + kb + 8];
#pragma unroll
                for (int mi = 0; mi < 2; mi++) {
                    mma_bf16(acc[mi][ni], aH[mi], bH);
                    mma_bf16(acc[mi][ni], aH[mi], bL);
                    mma_bf16(acc[mi][ni], aL[mi], bH);
                }
            }
        }
        __syncthreads();
    }

#pragma unroll
    for (int mi = 0; mi < 2; mi++) {
        const int r = row0 + wm * 32 + mi * 16 + g;
#pragma unroll
        for (int ni = 0; ni < 8; ni++) {
            const int cc = col0 + wn * 64 + ni * 8 + tq * 2;
            const float b0 = bias[cc], b1 = bias[cc + 1];
            *(float2*)(C + (size_t)r * ldc + cc) =
                make_float2(acc[mi][ni][0] + b0, acc[mi][ni][1] + b1);
            *(float2*)(C + (size_t)(r + 8) * ldc + cc) =
                make_float2(acc[mi][ni][2] + b0, acc[mi][ni][3] + b1);
        }
    }
}

// ---------------- split helpers ---------------------------------------------
__device__ __forceinline__ void split1(float v, __nv_bfloat16& h, __nv_bfloat16& l) {
    h = __float2bfloat16(v);
    l = __float2bfloat16(v - __bfloat162float(h));
}

// ---------------- prep kernels -----------------------------------------------
__global__ void prep_x(const float* __restrict__ x,
                       __nv_bfloat16* __restrict__ xh, __nv_bfloat16* __restrict__ xl) {
    const int idx = blockIdx.x * 256 + threadIdx.x;
    if (idx >= NN * KD) return;
    const int row = idx >> 8, col = idx & 255;
    const float v = (row < NREAL && col < 200) ? x[row * 200 + col] : 0.0f;
    split1(v, xh[idx], xl[idx]);
}
__global__ void prep_wred(const float* __restrict__ W,
                          __nv_bfloat16* __restrict__ wh, __nv_bfloat16* __restrict__ wl) {
    const int idx = blockIdx.x * 256 + threadIdx.x;
    if (idx >= 256 * KD) return;
    const int n = idx >> 8, k = idx & 255;
    const float v = (k < 200) ? W[n * 200 + k] : 0.0f;
    split1(v, wh[idx], wl[idx]);
}
__global__ void prep_whh(const float* __restrict__ W,
                         __nv_bfloat16* __restrict__ wh, __nv_bfloat16* __restrict__ wl) {
    const int idx = blockIdx.x * 256 + threadIdx.x;
    if (idx >= 768 * KD) return;
    split1(W[idx], wh[idx], wl[idx]);
}

// Wfused[t][o][k] = sum_c W_ih[o][c] * W_ggc[t][k][c-as-row]  -- i.e.
// B_fused = W_ih @ W_ggc[t]^T computed in fp32, split-written to planes.
// Tile 64x64, 256 threads (16x16, 4x4 per thread). grid (k/64, o/64, t).
__global__ void __launch_bounds__(256)
prep_wfused(const float* __restrict__ Wih, const float* __restrict__ Wggc,
            __nv_bfloat16* __restrict__ fh, __nv_bfloat16* __restrict__ fl)
{
    __shared__ float sA[16][65];   // [c][o]
    __shared__ float sB[16][65];   // [c][k]
    const int tid = threadIdx.x;
    const int tx = tid & 15, ty = tid >> 4;
    const int k0 = blockIdx.x * 64, o0 = blockIdx.y * 64;
    const int t  = blockIdx.z;
    const float* Wg = Wggc + (size_t)t * 65536;   // [k][c] row-major... careful

    // W_ggc[t] has shape [HID(k'), HID(c')] with element (k,c) at k*256+c where
    // m = h @ Wg means m[:,c] = sum_k h[:,k] Wg[k][c].  Fused: B[o][kk] =
    // sum_c Wih[o][c] * Wg[kk][c]?  NO: gi = S @ Wg @ Wih^T ->
    // B_fused[o][kk] = (Wg @ Wih^T)[kk][o] = sum_c Wg[kk][c] * Wih[o][c].
    float acc[4][4];
#pragma unroll
    for (int i = 0; i < 4; i++)
#pragma unroll
        for (int j = 0; j < 4; j++) acc[i][j] = 0.0f;

    for (int c0 = 0; c0 < 256; c0 += 16) {
        // load A tile: Wih rows o0..o0+63, cols c0..c0+15 -> sA[c][o]
        // 64*16 = 1024 elems, 256 threads x 4
#pragma unroll
        for (int i = 0; i < 4; i++) {
            const int idx = i * 256 + tid;
            const int oo = idx >> 4, cc = idx & 15;
            sA[cc][oo] = Wih[(size_t)(o0 + oo) * 256 + c0 + cc];
            sB[cc][oo] = Wg[(size_t)(k0 + oo) * 256 + c0 + cc];
        }
        __syncthreads();
#pragma unroll
        for (int c = 0; c < 16; c++) {
            float av[4], bv[4];
#pragma unroll
            for (int i = 0; i < 4; i++) av[i] = sA[c][ty * 4 + i];
#pragma unroll
            for (int j = 0; j < 4; j++) bv[j] = sB[c][tx * 4 + j];
#pragma unroll
            for (int i = 0; i < 4; i++)
#pragma unroll
                for (int j = 0; j < 4; j++)
                    acc[i][j] = fmaf(av[i], bv[j], acc[i][j]);
        }
        __syncthreads();
    }
#pragma unroll
    for (int i = 0; i < 4; i++) {
        const int o = o0 + ty * 4 + i;
#pragma unroll
        for (int j = 0; j < 4; j++) {
            const int k = k0 + tx * 4 + j;
            const size_t off = (size_t)t * 768 * KD + (size_t)o * KD + k;
            __nv_bfloat16 hh, ll;
            split1(acc[i][j], hh, ll);
            fh[off] = hh;
            fl[off] = ll;
        }
    }
}

__global__ void split_h(const float* __restrict__ h,
                        __nv_bfloat16* __restrict__ hh, __nv_bfloat16* __restrict__ hl) {
    const int idx = blockIdx.x * 256 + threadIdx.x;
    if (idx >= NN * HID) return;
    split1(h[idx], hh[idx], hl[idx]);
}

// ---------------- CSR build --------------------------------------------------
__global__ void hist_kernel(const int* __restrict__ ei, int* __restrict__ cnt) {
    const int e = blockIdx.x * 256 + threadIdx.x;
    if (e >= NE) return;
    atomicAdd(&cnt[ei[NE + e]], 1);
}
__global__ void scan_kernel(const int* __restrict__ cnt, int* __restrict__ rowptr) {
    __shared__ int s[1024];
    __shared__ int carryS;
    const int tid = threadIdx.x;
    if (tid == 0) { carryS = 0; rowptr[0] = 0; }
    __syncthreads();
    for (int base = 0; base < NN; base += 1024) {
        const int idx = base + tid;
        int v = (idx < NN) ? cnt[idx] : 0;
        s[tid] = v;
        __syncthreads();
        for (int off = 1; off < 1024; off <<= 1) {
            int t = (tid >= off) ? s[tid - off] : 0;
            __syncthreads();
            s[tid] += t;
            __syncthreads();
        }
        const int carry = carryS;
        if (idx < NN) rowptr[idx + 1] = carry + s[tid];
        __syncthreads();
        if (tid == 1023) carryS = carry + s[1023];
        __syncthreads();
    }
}
__global__ void copycur_kernel(const int* __restrict__ rowptr, int* __restrict__ cur) {
    const int i = blockIdx.x * 256 + threadIdx.x;
    if (i < NN) cur[i] = rowptr[i];
}
__global__ void fill_kernel(const int* __restrict__ ei, int* __restrict__ cur,
                            int* __restrict__ eidx) {
    const int e = blockIdx.x * 256 + threadIdx.x;
    if (e >= NE) return;
    const int pos = atomicAdd(&cur[ei[NE + e]], 1);
    eidx[pos] = ei[e];
}

// ---------------- aggregation: warp/dst-node gather of h -> bf16 planes ------
__global__ void agg_kernel(const float* __restrict__ h,
                           const int* __restrict__ rowptr, const int* __restrict__ eidx,
                           __nv_bfloat16* __restrict__ aggH, __nv_bfloat16* __restrict__ aggL)
{
    const int w = (blockIdx.x * blockDim.x + threadIdx.x) >> 5;
    const int lane = threadIdx.x & 31;
    if (w >= NN) return;
    const int beg = rowptr[w], end = rowptr[w + 1];
    float4 a0 = make_float4(0, 0, 0, 0), a1 = make_float4(0, 0, 0, 0);
    for (int i = beg; i < end; i++) {
        const int s = eidx[i];
        const float4* hr = (const float4*)(h + (size_t)s * 256);
        const float4 v0 = hr[lane * 2], v1 = hr[lane * 2 + 1];
        a0.x += v0.x; a0.y += v0.y; a0.z += v0.z; a0.w += v0.w;
        a1.x += v1.x; a1.y += v1.y; a1.z += v1.z; a1.w += v1.w;
    }
    const float vals[8] = {a0.x, a0.y, a0.z, a0.w, a1.x, a1.y, a1.z, a1.w};
    unsigned hb[4], lb[4];
#pragma unroll
    for (int q = 0; q < 4; q++) {
        __nv_bfloat16 h0, l0, h1, l1;
        split1(vals[2 * q], h0, l0);
        split1(vals[2 * q + 1], h1, l1);
        __nv_bfloat162 ph(h0, h1), pl(l0, l1);
        hb[q] = *(unsigned*)&ph;
        lb[q] = *(unsigned*)&pl;
    }
    *(uint4*)(aggH + (size_t)w * 256 + lane * 8) = make_uint4(hb[0], hb[1], hb[2], hb[3]);
    *(uint4*)(aggL + (size_t)w * 256 + lane * 8) = make_uint4(lb[0], lb[1], lb[2], lb[3]);
}

// ---------------- fused GRU --------------------------------------------------
__device__ __forceinline__ float sigf(float x) { return 1.0f / (1.0f + __expf(-x)); }

__global__ void gru_kernel(const float* __restrict__ gi_, const float* __restrict__ gh_,
                           float* __restrict__ h,
                           __nv_bfloat16* __restrict__ hh, __nv_bfloat16* __restrict__ hl)
{
    const int idx = blockIdx.x * blockDim.x + threadIdx.x;
    if (idx >= NN * 64) return;
    const int row = idx >> 6, c = (idx & 63) * 4;
    const float* gi = gi_ + (size_t)row * 768;
    const float* gh = gh_ + (size_t)row * 768;
    const float4 ir = *(const float4*)(gi + c);
    const float4 iz = *(const float4*)(gi + 256 + c);
    const float4 in = *(const float4*)(gi + 512 + c);
    const float4 hr = *(const float4*)(gh + c);
    const float4 hz = *(const float4*)(gh + 256 + c);
    const float4 hn = *(const float4*)(gh + 512 + c);
    float4* H = (float4*)(h + (size_t)row * 256 + c);
    const float4 hv = *H;

    float4 o;
    { float r = sigf(ir.x + hr.x), z = sigf(iz.x + hz.x);
      float n = tanhf(in.x + r * hn.x); o.x = (1.0f - z) * n + z * hv.x; }
    { float r = sigf(ir.y + hr.y), z = sigf(iz.y + hz.y);
      float n = tanhf(in.y + r * hn.y); o.y = (1.0f - z) * n + z * hv.y; }
    { float r = sigf(ir.z + hr.z), z = sigf(iz.z + hz.z);
      float n = tanhf(in.z + r * hn.z); o.z = (1.0f - z) * n + z * hv.z; }
    { float r = sigf(ir.w + hr.w), z = sigf(iz.w + hz.w);
      float n = tanhf(in.w + r * hn.w); o.w = (1.0f - z) * n + z * hv.w; }
    *H = o;

    __nv_bfloat16 h0, l0, h1, l1, h2, l2, h3, l3;
    split1(o.x, h0, l0); split1(o.y, h1, l1);
    split1(o.z, h2, l2); split1(o.w, h3, l3);
    __nv_bfloat162 p01(h0, h1), p23(h2, h3), q01(l0, l1), q23(l2, l3);
    *(__nv_bfloat162*)(hh + (size_t)row * 256 + c)     = p01;
    *(__nv_bfloat162*)(hh + (size_t)row * 256 + c + 2) = p23;
    *(__nv_bfloat162*)(hl + (size_t)row * 256 + c)     = q01;
    *(__nv_bfloat162*)(hl + (size_t)row * 256 + c + 2) = q23;
}

// ---------------- head -------------------------------------------------------
__global__ void head_kernel(const float* __restrict__ h,
                            const float* __restrict__ W_lin,
                            const float* __restrict__ b_lin,
                            float* __restrict__ out, int N)
{
    const int gt = blockIdx.x * blockDim.x + threadIdx.x;
    const int node = gt >> 5;
    const int lane = gt & 31;
    if (node >= N) return;
    const float4* hr = (const float4*)(h + (size_t)node * HID);
    const float4* w0 = (const float4*)(W_lin);
    const float4* w1 = (const float4*)(W_lin + HID);
    float a0 = 0.0f, a1 = 0.0f;
#pragma unroll
    for (int it = 0; it < 2; it++) {
        const int i = lane + it * 32;
        float4 v = hr[i];
        v.x = fmaxf(v.x, 0.f); v.y = fmaxf(v.y, 0.f);
        v.z = fmaxf(v.z, 0.f); v.w = fmaxf(v.w, 0.f);
        const float4 x0 = w0[i], x1 = w1[i];
        a0 += v.x * x0.x + v.y * x0.y + v.z * x0.z + v.w * x0.w;
        a1 += v.x * x1.x + v.y * x1.y + v.z * x1.z + v.w * x1.w;
    }
#pragma unroll
    for (int off = 16; off > 0; off >>= 1) {
        a0 += __shfl_down_sync(0xffffffffu, a0, off);
        a1 += __shfl_down_sync(0xffffffffu, a1, off);
    }
    if (lane == 0) {
        const float o0 = a0 + b_lin[0];
        const float o1 = a1 + b_lin[1];
        const float mx = fmaxf(o0, o1);
        const float lse = mx + logf(expf(o0 - mx) + expf(o1 - mx));
        out[(size_t)node * 2 + 0] = o0 - lse;
        out[(size_t)node * 2 + 1] = o1 - lse;
    }
}

// ---------------- launch -----------------------------------------------------
extern "C" void kernel_launch(void* const* d_in, const int* in_sizes, int n_in,
                              void* d_out, int out_size)
{
    const float* x        = (const float*)d_in[0];
    const int*   ei       = (const int*)  d_in[1];
    const float* W_reduce = (const float*)d_in[3];
    const float* b_reduce = (const float*)d_in[4];
    const float* W_ggc    = (const float*)d_in[5];
    const float* W_ih     = (const float*)d_in[6];
    const float* W_hh     = (const float*)d_in[7];
    const float* b_ih     = (const float*)d_in[8];
    const float* b_hh     = (const float*)d_in[9];
    const float* W_lin    = (const float*)d_in[10];
    const float* b_lin    = (const float*)d_in[11];
    float* out = (float*)d_out;

    float *h, *gh, *gi;
    __nv_bfloat16 *hH, *hL, *xH, *xL, *aggH, *aggL, *WfH, *WfL, *WhH, *WhL, *WrH, *WrL;
    int *cnt, *rowptr, *cur, *eidx;
    cudaGetSymbolAddress((void**)&h, g_h);
    cudaGetSymbolAddress((void**)&gh, g_gh);
    cudaGetSymbolAddress((void**)&gi, g_gi);
    cudaGetSymbolAddress((void**)&hH, g_hH);
    cudaGetSymbolAddress((void**)&hL, g_hL);
    cudaGetSymbolAddress((void**)&xH, g_xH);
    cudaGetSymbolAddress((void**)&xL, g_xL);
    cudaGetSymbolAddress((void**)&aggH, g_aggH);
    cudaGetSymbolAddress((void**)&aggL, g_aggL);
    cudaGetSymbolAddress((void**)&WfH, g_WfusH);
    cudaGetSymbolAddress((void**)&WfL, g_WfusL);
    cudaGetSymbolAddress((void**)&WhH, g_WhhH);
    cudaGetSymbolAddress((void**)&WhL, g_WhhL);
    cudaGetSymbolAddress((void**)&WrH, g_WredH);
    cudaGetSymbolAddress((void**)&WrL, g_WredL);
    cudaGetSymbolAddress((void**)&cnt, g_cnt);
    cudaGetSymbolAddress((void**)&rowptr, g_rowptr);
    cudaGetSymbolAddress((void**)&cur, g_cur);
    cudaGetSymbolAddress((void**)&eidx, g_eidx);

    cudaFuncSetAttribute(gemm_mma, cudaFuncAttributeMaxDynamicSharedMemorySize, GSMEM);

    // ---- preprocessing ----
    prep_x<<<(NN * KD + 255) / 256, 256>>>(x, xH, xL);
    prep_wred<<<(256 * KD + 255) / 256, 256>>>(W_reduce, WrH, WrL);
    prep_whh<<<(768 * KD + 255) / 256, 256>>>(W_hh, WhH, WhL);
    prep_wfused<<<dim3(4, 12, NSTEP), 256>>>(W_ih, W_ggc, WfH, WfL);
    cudaMemsetAsync(cnt, 0, NN * sizeof(int));
    hist_kernel<<<(NE + 255) / 256, 256>>>(ei, cnt);
    scan_kernel<<<1, 1024>>>(cnt, rowptr);
    copycur_kernel<<<(NN + 255) / 256, 256>>>(rowptr, cur);
    fill_kernel<<<(NE + 255) / 256, 256>>>(ei, cur, eidx);

    const int MB = NN / 128;   // 391

    // h = x @ W_reduce^T + b_reduce
    gemm_mma<<<dim3(2, MB), 256, GSMEM>>>(xH, xL, WrH, WrL, b_reduce, h, 256);
    split_h<<<(NN * HID + 255) / 256, 256>>>(h, hH, hL);

    for (int t = 0; t < NSTEP; t++) {
        // aggsum = segsum(h) as bf16 planes
        agg_kernel<<<(NN * 32 + 255) / 256, 256>>>(h, rowptr, eidx, aggH, aggL);
        // gi = aggsum @ Wfused[t]^T + b_ih
        gemm_mma<<<dim3(6, MB), 256, GSMEM>>>(
            aggH, aggL, WfH + (size_t)t * 768 * KD, WfL + (size_t)t * 768 * KD,
            b_ih, gi, 768);
        // gh = h @ W_hh^T + b_hh
        gemm_mma<<<dim3(6, MB), 256, GSMEM>>>(hH, hL, WhH, WhL, b_hh, gh, 768);
        // h = GRU(gi, gh, h); emit planes
        gru_kernel<<<(NN * 64 + 255) / 256, 256>>>(gi, gh, h, hH, hL);
    }

    head_kernel<<<(NREAL * 32 + 255) / 256, 256>>>(h, W_lin, b_lin, out, NREAL);
}

// round 7
// speedup vs baseline: 3.4355x; 1.0906x over previous
#include <cuda_runtime.h>
#include <cuda_bf16.h>
#include <math.h>
#include <stdint.h>

#define NN      50048      // padded node count (391 * 128)
#define NREAL   50000
#define NE      300000
#define KD      256        // padded K dim
#define HID     256
#define NSTEP   8

// ---------------- scratch (static device globals; no runtime alloc) ----------
__device__ float g_h  [NN * HID];
__device__ float g_gh [NN * 768];
__device__ float g_gi [NN * 768];
__device__ __nv_bfloat16 g_hH[NN * KD],  g_hL[NN * KD];
__device__ __nv_bfloat16 g_xH[NN * KD],  g_xL[NN * KD];
__device__ __nv_bfloat16 g_aggH[NN * KD], g_aggL[NN * KD];
__device__ __nv_bfloat16 g_WfusH[NSTEP * 768 * KD], g_WfusL[NSTEP * 768 * KD];
__device__ __nv_bfloat16 g_WhhH[768 * KD], g_WhhL[768 * KD];
__device__ __nv_bfloat16 g_WredH[256 * KD], g_WredL[256 * KD];
__device__ int g_cnt[NN], g_rowptr[NN + 1], g_cur[NN], g_eidx[NE];

// ---------------- mma.sync bf16-split GEMM (ldmatrix) ------------------------
// C[M,N] = A@B^T + bias.  A planes [M][256] hi/lo, B planes [N][256] hi/lo.
// Split product: C = Ah*Bh + Ah*Bl + Al*Bh.
#define BK    32
#define SA    40                       // row stride in bf16 elems (80B)
#define PLANEB (128 * SA * 2)          // 10240 B per plane
#define STAGEB (4 * PLANEB)            // 40960 B per stage
#define GSMEM  (2 * STAGEB)            // 81920 B

struct GemmArgs {
    const __nv_bfloat16 *AH, *AL, *BH, *BL;
    const float* bias;
    float* C;
    int ldc;
};

__device__ __forceinline__ void mma_bf16(float* c, const unsigned* a, const unsigned* b)
{
    asm volatile(
        "mma.sync.aligned.m16n8k16.row.col.f32.bf16.bf16.f32 "
        "{%0,%1,%2,%3}, {%4,%5,%6,%7}, {%8,%9}, {%0,%1,%2,%3};\n"
        : "+f"(c[0]), "+f"(c[1]), "+f"(c[2]), "+f"(c[3])
        : "r"(a[0]), "r"(a[1]), "r"(a[2]), "r"(a[3]), "r"(b[0]), "r"(b[1]));
}
__device__ __forceinline__ void ldsm4(unsigned* r, uint32_t addr)
{
    asm volatile("ldmatrix.sync.aligned.m8n8.x4.shared.b16 {%0,%1,%2,%3}, [%4];"
                 : "=r"(r[0]), "=r"(r[1]), "=r"(r[2]), "=r"(r[3]) : "r"(addr));
}

__global__ void __launch_bounds__(256, 2)
gemm_mma(GemmArgs A0, GemmArgs A1)
{
    extern __shared__ char sm[];
    const GemmArgs& P = blockIdx.z ? A1 : A0;
    const uint32_t sb = (uint32_t)__cvta_generic_to_shared(sm);
    const int tid  = threadIdx.x;
    const int lane = tid & 31;
    const int warp = tid >> 5;
    const int wm   = warp & 3;
    const int wn   = warp >> 2;
    const int row0 = blockIdx.y * 128;
    const int col0 = blockIdx.x * 128;
    const int g    = lane >> 2;
    const int tq   = lane & 3;

    // ldmatrix per-lane byte offsets (within a stage)
    // A fragment (m16k16): lanes 0-15 rows 0-15 @k0, lanes 16-31 rows 0-15 @k+8
    const int a_row = wm * 32 + (lane & 15);
    const int a_kx  = (lane >> 4) * 16;                 // bytes
    const uint32_t aoffH0 = (uint32_t)(a_row * SA * 2 + a_kx);           // mi=0
    const uint32_t aoffH1 = aoffH0 + 16 * SA * 2;                         // mi=1
    // B fragment pairs (2 col-groups per ldmatrix.x4):
    // lanes0-7: cols c..c+7 @k0 ; 8-15: same cols @k+8 ; 16-23: cols+8 @k0 ; 24-31: cols+8 @k+8
    const int b_col = wn * 64 + (lane & 7) + ((lane >> 4) & 1) * 8;
    const int b_kx  = ((lane >> 3) & 1) * 16;           // bytes
    const uint32_t boff0 = (uint32_t)(b_col * SA * 2 + b_kx);

    const __nv_bfloat16* gA[2] = {P.AH, P.AL};
    const __nv_bfloat16* gB[2] = {P.BH, P.BL};

    auto copy_stage = [&](int st, int kc) {
        const int k0 = kc * BK;
        char* dst0 = sm + st * STAGEB;
#pragma unroll
        for (int i = 0; i < 8; i++) {
            const int idx = i * 256 + tid;
            const int p = idx >> 9;
            const int r = (idx >> 2) & 127;
            const int j = idx & 3;
            const __nv_bfloat16* gp = (p < 2) ? gA[p] : gB[p - 2];
            const int grow = ((p < 2) ? row0 : col0) + r;
            const void* src = gp + (size_t)grow * KD + k0 + j * 8;
            char* dst = dst0 + p * PLANEB + r * (SA * 2) + j * 16;
            asm volatile("cp.async.cg.shared.global [%0], [%1], 16;"
                         :: "l"((uint64_t)__cvta_generic_to_shared(dst)), "l"(src)
                         : "memory");
        }
        asm volatile("cp.async.commit_group;" ::: "memory");
    };

    float acc[2][8][4];
#pragma unroll
    for (int mi = 0; mi < 2; mi++)
#pragma unroll
        for (int ni = 0; ni < 8; ni++)
#pragma unroll
            for (int j = 0; j < 4; j++) acc[mi][ni][j] = 0.0f;

    copy_stage(0, 0);

    const int NCHUNK = KD / BK;
    for (int c = 0; c < NCHUNK; c++) {
        const int st = c & 1;
        if (c + 1 < NCHUNK) {
            copy_stage(st ^ 1, c + 1);
            asm volatile("cp.async.wait_group 1;" ::: "memory");
        } else {
            asm volatile("cp.async.wait_group 0;" ::: "memory");
        }
        __syncthreads();

        const uint32_t base = sb + st * STAGEB;
#pragma unroll
        for (int ks = 0; ks < 2; ks++) {
            const uint32_t kso = ks * 32;               // 16 elems = 32 bytes
            unsigned aH[2][4], aL[2][4];
            ldsm4(aH[0], base + 0 * PLANEB + aoffH0 + kso);
            ldsm4(aH[1], base + 0 * PLANEB + aoffH1 + kso);
            ldsm4(aL[0], base + 1 * PLANEB + aoffH0 + kso);
            ldsm4(aL[1], base + 1 * PLANEB + aoffH1 + kso);
#pragma unroll
            for (int ni2 = 0; ni2 < 8; ni2 += 2) {
                unsigned bH[4], bL[4];
                const uint32_t bo = boff0 + (uint32_t)(ni2 * 8 * SA * 2) + kso;
                ldsm4(bH, base + 2 * PLANEB + bo);
                ldsm4(bL, base + 3 * PLANEB + bo);
#pragma unroll
                for (int q = 0; q < 2; q++) {
#pragma unroll
                    for (int mi = 0; mi < 2; mi++) {
                        mma_bf16(acc[mi][ni2 + q], aH[mi], bH + q * 2);
                        mma_bf16(acc[mi][ni2 + q], aH[mi], bL + q * 2);
                        mma_bf16(acc[mi][ni2 + q], aL[mi], bH + q * 2);
                    }
                }
            }
        }
        __syncthreads();
    }

#pragma unroll
    for (int mi = 0; mi < 2; mi++) {
        const int r = row0 + wm * 32 + mi * 16 + g;
#pragma unroll
        for (int ni = 0; ni < 8; ni++) {
            const int cc = col0 + wn * 64 + ni * 8 + tq * 2;
            const float b0 = P.bias[cc], b1 = P.bias[cc + 1];
            *(float2*)(P.C + (size_t)r * P.ldc + cc) =
                make_float2(acc[mi][ni][0] + b0, acc[mi][ni][1] + b1);
            *(float2*)(P.C + (size_t)(r + 8) * P.ldc + cc) =
                make_float2(acc[mi][ni][2] + b0, acc[mi][ni][3] + b1);
        }
    }
}

// ---------------- split helpers ---------------------------------------------
__device__ __forceinline__ void split1(float v, __nv_bfloat16& h, __nv_bfloat16& l) {
    h = __float2bfloat16(v);
    l = __float2bfloat16(v - __bfloat162float(h));
}

// ---------------- prep kernels -----------------------------------------------
__global__ void prep_x(const float* __restrict__ x,
                       __nv_bfloat16* __restrict__ xh, __nv_bfloat16* __restrict__ xl) {
    const int idx = blockIdx.x * 256 + threadIdx.x;
    if (idx >= NN * KD) return;
    const int row = idx >> 8, col = idx & 255;
    const float v = (row < NREAL && col < 200) ? x[row * 200 + col] : 0.0f;
    split1(v, xh[idx], xl[idx]);
}
__global__ void prep_wred(const float* __restrict__ W,
                          __nv_bfloat16* __restrict__ wh, __nv_bfloat16* __restrict__ wl) {
    const int idx = blockIdx.x * 256 + threadIdx.x;
    if (idx >= 256 * KD) return;
    const int n = idx >> 8, k = idx & 255;
    const float v = (k < 200) ? W[n * 200 + k] : 0.0f;
    split1(v, wh[idx], wl[idx]);
}
__global__ void prep_whh(const float* __restrict__ W,
                         __nv_bfloat16* __restrict__ wh, __nv_bfloat16* __restrict__ wl) {
    const int idx = blockIdx.x * 256 + threadIdx.x;
    if (idx >= 768 * KD) return;
    split1(W[idx], wh[idx], wl[idx]);
}

// B_fused[t][o][k] = sum_c W_ggc[t][k][c] * W_ih[o][c]   (fp32, then split)
__global__ void __launch_bounds__(256)
prep_wfused(const float* __restrict__ Wih, const float* __restrict__ Wggc,
            __nv_bfloat16* __restrict__ fh, __nv_bfloat16* __restrict__ fl)
{
    __shared__ float sA[16][65];   // [c][o]
    __shared__ float sB[16][65];   // [c][k]
    const int tid = threadIdx.x;
    const int tx = tid & 15, ty = tid >> 4;
    const int k0 = blockIdx.x * 64, o0 = blockIdx.y * 64;
    const int t  = blockIdx.z;
    const float* Wg = Wggc + (size_t)t * 65536;

    float acc[4][4];
#pragma unroll
    for (int i = 0; i < 4; i++)
#pragma unroll
        for (int j = 0; j < 4; j++) acc[i][j] = 0.0f;

    for (int c0 = 0; c0 < 256; c0 += 16) {
#pragma unroll
        for (int i = 0; i < 4; i++) {
            const int idx = i * 256 + tid;
            const int oo = idx >> 4, cc = idx & 15;
            sA[cc][oo] = Wih[(size_t)(o0 + oo) * 256 + c0 + cc];
            sB[cc][oo] = Wg[(size_t)(k0 + oo) * 256 + c0 + cc];
        }
        __syncthreads();
#pragma unroll
        for (int c = 0; c < 16; c++) {
            float av[4], bv[4];
#pragma unroll
            for (int i = 0; i < 4; i++) av[i] = sA[c][ty * 4 + i];
#pragma unroll
            for (int j = 0; j < 4; j++) bv[j] = sB[c][tx * 4 + j];
#pragma unroll
            for (int i = 0; i < 4; i++)
#pragma unroll
                for (int j = 0; j < 4; j++)
                    acc[i][j] = fmaf(av[i], bv[j], acc[i][j]);
        }
        __syncthreads();
    }
#pragma unroll
    for (int i = 0; i < 4; i++) {
        const int o = o0 + ty * 4 + i;
#pragma unroll
        for (int j = 0; j < 4; j++) {
            const int k = k0 + tx * 4 + j;
            const size_t off = (size_t)t * 768 * KD + (size_t)o * KD + k;
            __nv_bfloat16 hh, ll;
            split1(acc[i][j], hh, ll);
            fh[off] = hh;
            fl[off] = ll;
        }
    }
}

__global__ void split_h(const float* __restrict__ h,
                        __nv_bfloat16* __restrict__ hh, __nv_bfloat16* __restrict__ hl) {
    const int idx = blockIdx.x * 256 + threadIdx.x;
    if (idx >= NN * HID) return;
    split1(h[idx], hh[idx], hl[idx]);
}

// ---------------- CSR build --------------------------------------------------
__global__ void hist_kernel(const int* __restrict__ ei, int* __restrict__ cnt) {
    const int e = blockIdx.x * 256 + threadIdx.x;
    if (e >= NE) return;
    atomicAdd(&cnt[ei[NE + e]], 1);
}
__global__ void scan_kernel(const int* __restrict__ cnt, int* __restrict__ rowptr) {
    __shared__ int s[1024];
    __shared__ int carryS;
    const int tid = threadIdx.x;
    if (tid == 0) { carryS = 0; rowptr[0] = 0; }
    __syncthreads();
    for (int base = 0; base < NN; base += 1024) {
        const int idx = base + tid;
        int v = (idx < NN) ? cnt[idx] : 0;
        s[tid] = v;
        __syncthreads();
        for (int off = 1; off < 1024; off <<= 1) {
            int t = (tid >= off) ? s[tid - off] : 0;
            __syncthreads();
            s[tid] += t;
            __syncthreads();
        }
        const int carry = carryS;
        if (idx < NN) rowptr[idx + 1] = carry + s[tid];
        __syncthreads();
        if (tid == 1023) carryS = carry + s[1023];
        __syncthreads();
    }
}
__global__ void copycur_kernel(const int* __restrict__ rowptr, int* __restrict__ cur) {
    const int i = blockIdx.x * 256 + threadIdx.x;
    if (i < NN) cur[i] = rowptr[i];
}
__global__ void fill_kernel(const int* __restrict__ ei, int* __restrict__ cur,
                            int* __restrict__ eidx) {
    const int e = blockIdx.x * 256 + threadIdx.x;
    if (e >= NE) return;
    const int pos = atomicAdd(&cur[ei[NE + e]], 1);
    eidx[pos] = ei[e];
}

// ---------------- aggregation: warp/dst-node gather of h -> bf16 planes ------
__global__ void agg_kernel(const float* __restrict__ h,
                           const int* __restrict__ rowptr, const int* __restrict__ eidx,
                           __nv_bfloat16* __restrict__ aggH, __nv_bfloat16* __restrict__ aggL)
{
    const int w = (blockIdx.x * blockDim.x + threadIdx.x) >> 5;
    const int lane = threadIdx.x & 31;
    if (w >= NN) return;
    const int beg = rowptr[w], end = rowptr[w + 1];
    float4 a0 = make_float4(0, 0, 0, 0), a1 = make_float4(0, 0, 0, 0);
    for (int i = beg; i < end; i++) {
        const int s = eidx[i];
        const float4* hr = (const float4*)(h + (size_t)s * 256);
        const float4 v0 = hr[lane * 2], v1 = hr[lane * 2 + 1];
        a0.x += v0.x; a0.y += v0.y; a0.z += v0.z; a0.w += v0.w;
        a1.x += v1.x; a1.y += v1.y; a1.z += v1.z; a1.w += v1.w;
    }
    const float vals[8] = {a0.x, a0.y, a0.z, a0.w, a1.x, a1.y, a1.z, a1.w};
    unsigned hb[4], lb[4];
#pragma unroll
    for (int q = 0; q < 4; q++) {
        __nv_bfloat16 h0, l0, h1, l1;
        split1(vals[2 * q], h0, l0);
        split1(vals[2 * q + 1], h1, l1);
        __nv_bfloat162 ph(h0, h1), pl(l0, l1);
        hb[q] = *(unsigned*)&ph;
        lb[q] = *(unsigned*)&pl;
    }
    *(uint4*)(aggH + (size_t)w * 256 + lane * 8) = make_uint4(hb[0], hb[1], hb[2], hb[3]);
    *(uint4*)(aggL + (size_t)w * 256 + lane * 8) = make_uint4(lb[0], lb[1], lb[2], lb[3]);
}

// ---------------- fused GRU --------------------------------------------------
__device__ __forceinline__ float sigf(float x) { return 1.0f / (1.0f + __expf(-x)); }

__global__ void gru_kernel(const float* __restrict__ gi_, const float* __restrict__ gh_,
                           float* __restrict__ h,
                           __nv_bfloat16* __restrict__ hh, __nv_bfloat16* __restrict__ hl)
{
    const int idx = blockIdx.x * blockDim.x + threadIdx.x;
    if (idx >= NN * 64) return;
    const int row = idx >> 6, c = (idx & 63) * 4;
    const float* gi = gi_ + (size_t)row * 768;
    const float* gh = gh_ + (size_t)row * 768;
    const float4 ir = *(const float4*)(gi + c);
    const float4 iz = *(const float4*)(gi + 256 + c);
    const float4 in = *(const float4*)(gi + 512 + c);
    const float4 hr = *(const float4*)(gh + c);
    const float4 hz = *(const float4*)(gh + 256 + c);
    const float4 hn = *(const float4*)(gh + 512 + c);
    float4* H = (float4*)(h + (size_t)row * 256 + c);
    const float4 hv = *H;

    float4 o;
    { float r = sigf(ir.x + hr.x), z = sigf(iz.x + hz.x);
      float n = tanhf(in.x + r * hn.x); o.x = (1.0f - z) * n + z * hv.x; }
    { float r = sigf(ir.y + hr.y), z = sigf(iz.y + hz.y);
      float n = tanhf(in.y + r * hn.y); o.y = (1.0f - z) * n + z * hv.y; }
    { float r = sigf(ir.z + hr.z), z = sigf(iz.z + hz.z);
      float n = tanhf(in.z + r * hn.z); o.z = (1.0f - z) * n + z * hv.z; }
    { float r = sigf(ir.w + hr.w), z = sigf(iz.w + hz.w);
      float n = tanhf(in.w + r * hn.w); o.w = (1.0f - z) * n + z * hv.w; }
    *H = o;

    __nv_bfloat16 h0, l0, h1, l1, h2, l2, h3, l3;
    split1(o.x, h0, l0); split1(o.y, h1, l1);
    split1(o.z, h2, l2); split1(o.w, h3, l3);
    __nv_bfloat162 p01(h0, h1), p23(h2, h3), q01(l0, l1), q23(l2, l3);
    *(__nv_bfloat162*)(hh + (size_t)row * 256 + c)     = p01;
    *(__nv_bfloat162*)(hh + (size_t)row * 256 + c + 2) = p23;
    *(__nv_bfloat162*)(hl + (size_t)row * 256 + c)     = q01;
    *(__nv_bfloat162*)(hl + (size_t)row * 256 + c + 2) = q23;
}

// ---------------- head -------------------------------------------------------
__global__ void head_kernel(const float* __restrict__ h,
                            const float* __restrict__ W_lin,
                            const float* __restrict__ b_lin,
                            float* __restrict__ out, int N)
{
    const int gt = blockIdx.x * blockDim.x + threadIdx.x;
    const int node = gt >> 5;
    const int lane = gt & 31;
    if (node >= N) return;
    const float4* hr = (const float4*)(h + (size_t)node * HID);
    const float4* w0 = (const float4*)(W_lin);
    const float4* w1 = (const float4*)(W_lin + HID);
    float a0 = 0.0f, a1 = 0.0f;
#pragma unroll
    for (int it = 0; it < 2; it++) {
        const int i = lane + it * 32;
        float4 v = hr[i];
        v.x = fmaxf(v.x, 0.f); v.y = fmaxf(v.y, 0.f);
        v.z = fmaxf(v.z, 0.f); v.w = fmaxf(v.w, 0.f);
        const float4 x0 = w0[i], x1 = w1[i];
        a0 += v.x * x0.x + v.y * x0.y + v.z * x0.z + v.w * x0.w;
        a1 += v.x * x1.x + v.y * x1.y + v.z * x1.z + v.w * x1.w;
    }
#pragma unroll
    for (int off = 16; off > 0; off >>= 1) {
        a0 += __shfl_down_sync(0xffffffffu, a0, off);
        a1 += __shfl_down_sync(0xffffffffu, a1, off);
    }
    if (lane == 0) {
        const float o0 = a0 + b_lin[0];
        const float o1 = a1 + b_lin[1];
        const float mx = fmaxf(o0, o1);
        const float lse = mx + logf(expf(o0 - mx) + expf(o1 - mx));
        out[(size_t)node * 2 + 0] = o0 - lse;
        out[(size_t)node * 2 + 1] = o1 - lse;
    }
}

// ---------------- launch -----------------------------------------------------
extern "C" void kernel_launch(void* const* d_in, const int* in_sizes, int n_in,
                              void* d_out, int out_size)
{
    const float* x        = (const float*)d_in[0];
    const int*   ei       = (const int*)  d_in[1];
    const float* W_reduce = (const float*)d_in[3];
    const float* b_reduce = (const float*)d_in[4];
    const float* W_ggc    = (const float*)d_in[5];
    const float* W_ih     = (const float*)d_in[6];
    const float* W_hh     = (const float*)d_in[7];
    const float* b_ih     = (const float*)d_in[8];
    const float* b_hh     = (const float*)d_in[9];
    const float* W_lin    = (const float*)d_in[10];
    const float* b_lin    = (const float*)d_in[11];
    float* out = (float*)d_out;

    float *h, *gh, *gi;
    __nv_bfloat16 *hH, *hL, *xH, *xL, *aggH, *aggL, *WfH, *WfL, *WhH, *WhL, *WrH, *WrL;
    int *cnt, *rowptr, *cur, *eidx;
    cudaGetSymbolAddress((void**)&h, g_h);
    cudaGetSymbolAddress((void**)&gh, g_gh);
    cudaGetSymbolAddress((void**)&gi, g_gi);
    cudaGetSymbolAddress((void**)&hH, g_hH);
    cudaGetSymbolAddress((void**)&hL, g_hL);
    cudaGetSymbolAddress((void**)&xH, g_xH);
    cudaGetSymbolAddress((void**)&xL, g_xL);
    cudaGetSymbolAddress((void**)&aggH, g_aggH);
    cudaGetSymbolAddress((void**)&aggL, g_aggL);
    cudaGetSymbolAddress((void**)&WfH, g_WfusH);
    cudaGetSymbolAddress((void**)&WfL, g_WfusL);
    cudaGetSymbolAddress((void**)&WhH, g_WhhH);
    cudaGetSymbolAddress((void**)&WhL, g_WhhL);
    cudaGetSymbolAddress((void**)&WrH, g_WredH);
    cudaGetSymbolAddress((void**)&WrL, g_WredL);
    cudaGetSymbolAddress((void**)&cnt, g_cnt);
    cudaGetSymbolAddress((void**)&rowptr, g_rowptr);
    cudaGetSymbolAddress((void**)&cur, g_cur);
    cudaGetSymbolAddress((void**)&eidx, g_eidx);

    cudaFuncSetAttribute(gemm_mma, cudaFuncAttributeMaxDynamicSharedMemorySize, GSMEM);

    // ---- preprocessing ----
    prep_x<<<(NN * KD + 255) / 256, 256>>>(x, xH, xL);
    prep_wred<<<(256 * KD + 255) / 256, 256>>>(W_reduce, WrH, WrL);
    prep_whh<<<(768 * KD + 255) / 256, 256>>>(W_hh, WhH, WhL);
    prep_wfused<<<dim3(4, 12, NSTEP), 256>>>(W_ih, W_ggc, WfH, WfL);
    cudaMemsetAsync(cnt, 0, NN * sizeof(int));
    hist_kernel<<<(NE + 255) / 256, 256>>>(ei, cnt);
    scan_kernel<<<1, 1024>>>(cnt, rowptr);
    copycur_kernel<<<(NN + 255) / 256, 256>>>(rowptr, cur);
    fill_kernel<<<(NE + 255) / 256, 256>>>(ei, cur, eidx);

    const int MB = NN / 128;   // 391

    // h = x @ W_reduce^T + b_reduce
    GemmArgs ar = {xH, xL, WrH, WrL, b_reduce, h, 256};
    gemm_mma<<<dim3(2, MB, 1), 256, GSMEM>>>(ar, ar);
    split_h<<<(NN * HID + 255) / 256, 256>>>(h, hH, hL);

    for (int t = 0; t < NSTEP; t++) {
        // aggsum = segsum(h) as bf16 planes
        agg_kernel<<<(NN * 32 + 255) / 256, 256>>>(h, rowptr, eidx, aggH, aggL);
        // gi = aggsum @ Wfused[t]^T + b_ih  AND  gh = h @ W_hh^T + b_hh (one launch)
        GemmArgs a_gi = {aggH, aggL, WfH + (size_t)t * 768 * KD,
                         WfL + (size_t)t * 768 * KD, b_ih, gi, 768};
        GemmArgs a_gh = {hH, hL, WhH, WhL, b_hh, gh, 768};
        gemm_mma<<<dim3(6, MB, 2), 256, GSMEM>>>(a_gi, a_gh);
        // h = GRU(gi, gh, h); emit planes
        gru_kernel<<<(NN * 64 + 255) / 256, 256>>>(gi, gh, h, hH, hL);
    }

    head_kernel<<<(NREAL * 32 + 255) / 256, 256>>>(h, W_lin, b_lin, out, NREAL);
}

// round 8
// speedup vs baseline: 3.5812x; 1.0424x over previous
#include <cuda_runtime.h>
#include <cuda_bf16.h>
#include <math.h>
#include <stdint.h>

#define NN      50048      // padded node count (391 * 128)
#define NREAL   50000
#define NE      300000
#define KD      256
#define HID     256
#define NSTEP   8

// ---------------- scratch (static device globals; no runtime alloc) ----------
__device__ float g_h    [NN * HID];
__device__ float g_gates[NN * 1024];       // [r_sum | z_sum | i_n | h_n]
__device__ __nv_bfloat16 g_hH[NN * KD],   g_hL[NN * KD];
__device__ __nv_bfloat16 g_xH[NN * KD],   g_xL[NN * KD];
__device__ __nv_bfloat16 g_aggH[NN * KD], g_aggL[NN * KD];
__device__ __nv_bfloat16 g_WfusH[NSTEP * 768 * KD], g_WfusL[NSTEP * 768 * KD];
__device__ __nv_bfloat16 g_WhhH[768 * KD], g_WhhL[768 * KD];
__device__ __nv_bfloat16 g_WredH[256 * KD], g_WredL[256 * KD];
__device__ float g_cbias[1024];
__device__ int g_cnt[NN], g_rowptr[NN + 1], g_cur[NN], g_eidx[NE];

// ---------------- shared GEMM machinery --------------------------------------
#define BK    32
#define SA    40                       // smem row stride in bf16 elems (80B)
#define PLANEB (128 * SA * 2)          // 10240 B per plane
#define STAGEB (4 * PLANEB)            // 40960 B per stage
#define GSMEM  (2 * STAGEB)            // 81920 B

__device__ __forceinline__ void mma_bf16(float* c, const unsigned* a, const unsigned* b)
{
    asm volatile(
        "mma.sync.aligned.m16n8k16.row.col.f32.bf16.bf16.f32 "
        "{%0,%1,%2,%3}, {%4,%5,%6,%7}, {%8,%9}, {%0,%1,%2,%3};\n"
        : "+f"(c[0]), "+f"(c[1]), "+f"(c[2]), "+f"(c[3])
        : "r"(a[0]), "r"(a[1]), "r"(a[2]), "r"(a[3]), "r"(b[0]), "r"(b[1]));
}
__device__ __forceinline__ void ldsm4(unsigned* r, uint32_t addr)
{
    asm volatile("ldmatrix.sync.aligned.m8n8.x4.shared.b16 {%0,%1,%2,%3}, [%4];"
                 : "=r"(r[0]), "=r"(r[1]), "=r"(r[2]), "=r"(r[3]) : "r"(addr));
}
__device__ __forceinline__ void cpasync16(char* dst, const void* src)
{
    asm volatile("cp.async.cg.shared.global [%0], [%1], 16;"
                 :: "l"((uint64_t)__cvta_generic_to_shared(dst)), "l"(src) : "memory");
}

// Compute-core over a staged tile; shared by both GEMM kernels.
// acc[2][8][4]; fragments via ldmatrix; 3-product split.
#define GEMM_COMPUTE(base)                                                     \
    do {                                                                       \
        _Pragma("unroll")                                                      \
        for (int ks = 0; ks < 2; ks++) {                                       \
            const uint32_t kso = ks * 32;                                      \
            unsigned aH[2][4], aL[2][4];                                       \
            ldsm4(aH[0], (base) + 0 * PLANEB + aoffH0 + kso);                  \
            ldsm4(aH[1], (base) + 0 * PLANEB + aoffH1 + kso);                  \
            ldsm4(aL[0], (base) + 1 * PLANEB + aoffH0 + kso);                  \
            ldsm4(aL[1], (base) + 1 * PLANEB + aoffH1 + kso);                  \
            _Pragma("unroll")                                                  \
            for (int ni2 = 0; ni2 < 8; ni2 += 2) {                             \
                unsigned bH[4], bL[4];                                         \
                const uint32_t bo = boff0 + (uint32_t)(ni2 * 8 * SA * 2) + kso;\
                ldsm4(bH, (base) + 2 * PLANEB + bo);                           \
                ldsm4(bL, (base) + 3 * PLANEB + bo);                           \
                _Pragma("unroll")                                              \
                for (int q = 0; q < 2; q++)                                    \
                    _Pragma("unroll")                                          \
                    for (int mi = 0; mi < 2; mi++) {                           \
                        mma_bf16(acc[mi][ni2 + q], aH[mi], bH + q * 2);        \
                        mma_bf16(acc[mi][ni2 + q], aH[mi], bL + q * 2);        \
                        mma_bf16(acc[mi][ni2 + q], aL[mi], bH + q * 2);        \
                    }                                                          \
            }                                                                  \
        }                                                                      \
    } while (0)

#define FRAG_SETUP()                                                           \
    const int tid  = threadIdx.x;                                              \
    const int lane = tid & 31;                                                 \
    const int warp = tid >> 5;                                                 \
    const int wm   = warp & 3;                                                 \
    const int wn   = warp >> 2;                                                \
    const int g    = lane >> 2;                                                \
    const int tq   = lane & 3;                                                 \
    const int a_row = wm * 32 + (lane & 15);                                   \
    const int a_kx  = (lane >> 4) * 16;                                        \
    const uint32_t aoffH0 = (uint32_t)(a_row * SA * 2 + a_kx);                 \
    const uint32_t aoffH1 = aoffH0 + 16 * SA * 2;                              \
    const int b_col = wn * 64 + (lane & 7) + ((lane >> 4) & 1) * 8;            \
    const int b_kx  = ((lane >> 3) & 1) * 16;                                  \
    const uint32_t boff0 = (uint32_t)(b_col * SA * 2 + b_kx)

// ---------------- init GEMM: h = x @ W_red^T + b -----------------------------
__global__ void __launch_bounds__(256, 2)
gemm_init(const __nv_bfloat16* __restrict__ AH, const __nv_bfloat16* __restrict__ AL,
          const __nv_bfloat16* __restrict__ BH, const __nv_bfloat16* __restrict__ BL,
          const float* __restrict__ bias, float* __restrict__ C, int ldc)
{
    extern __shared__ char sm[];
    const uint32_t sb = (uint32_t)__cvta_generic_to_shared(sm);
    FRAG_SETUP();
    const int row0 = blockIdx.y * 128, col0 = blockIdx.x * 128;
    const __nv_bfloat16* gp[4] = {AH, AL, BH, BL};

    auto copy_stage = [&](int st, int kc) {
        const int k0 = kc * BK;
        char* dst0 = sm + st * STAGEB;
#pragma unroll
        for (int i = 0; i < 8; i++) {
            const int idx = i * 256 + tid;
            const int p = idx >> 9, r = (idx >> 2) & 127, j = idx & 3;
            const int grow = ((p < 2) ? row0 : col0) + r;
            cpasync16(dst0 + p * PLANEB + r * (SA * 2) + j * 16,
                      gp[p] + (size_t)grow * KD + k0 + j * 8);
        }
        asm volatile("cp.async.commit_group;" ::: "memory");
    };

    float acc[2][8][4];
#pragma unroll
    for (int mi = 0; mi < 2; mi++)
#pragma unroll
        for (int ni = 0; ni < 8; ni++)
#pragma unroll
            for (int j = 0; j < 4; j++) acc[mi][ni][j] = 0.0f;

    copy_stage(0, 0);
    const int NCHUNK = KD / BK;
    for (int c = 0; c < NCHUNK; c++) {
        const int st = c & 1;
        if (c + 1 < NCHUNK) { copy_stage(st ^ 1, c + 1);
            asm volatile("cp.async.wait_group 1;" ::: "memory");
        } else asm volatile("cp.async.wait_group 0;" ::: "memory");
        __syncthreads();
        GEMM_COMPUTE(sb + st * STAGEB);
        __syncthreads();
    }
#pragma unroll
    for (int mi = 0; mi < 2; mi++) {
        const int r = row0 + wm * 32 + mi * 16 + g;
#pragma unroll
        for (int ni = 0; ni < 8; ni++) {
            const int cc = col0 + wn * 64 + ni * 8 + tq * 2;
            const float b0 = bias[cc], b1 = bias[cc + 1];
            *(float2*)(C + (size_t)r * ldc + cc) =
                make_float2(acc[mi][ni][0] + b0, acc[mi][ni][1] + b1);
            *(float2*)(C + (size_t)(r + 8) * ldc + cc) =
                make_float2(acc[mi][ni][2] + b0, acc[mi][ni][3] + b1);
        }
    }
}

// ---------------- step GEMM: gates = [agg|h] @ B'^T + cbias ------------------
// Output cols: 0-511 r_sum,z_sum (K=512); 512-767 i_n (K=0..255, A=agg,B=Wf);
// 768-1023 h_n (K=256..511, A=h, B=Whh rows 512-767).
__global__ void __launch_bounds__(256, 2)
gemm_step(const __nv_bfloat16* __restrict__ aggH, const __nv_bfloat16* __restrict__ aggL,
          const __nv_bfloat16* __restrict__ hH,   const __nv_bfloat16* __restrict__ hL,
          const __nv_bfloat16* __restrict__ WfH,  const __nv_bfloat16* __restrict__ WfL,
          const __nv_bfloat16* __restrict__ WhhH, const __nv_bfloat16* __restrict__ WhhL,
          const float* __restrict__ cbias, float* __restrict__ C)
{
    extern __shared__ char sm[];
    const uint32_t sb = (uint32_t)__cvta_generic_to_shared(sm);
    FRAG_SETUP();
    const int bx   = blockIdx.x;
    const int row0 = blockIdx.y * 128, col0 = bx * 128;

    int kbeg, kend;
    if (bx < 4)      { kbeg = 0; kend = 16; }
    else if (bx < 6) { kbeg = 0; kend = 8;  }
    else             { kbeg = 8; kend = 16; }

    auto copy_stage = [&](int st, int kc) {
        const int k0 = kc * BK;                 // global K 0..511
        const bool hi = k0 >= 256;
        const int ka = hi ? k0 - 256 : k0;      // K within plane
        const __nv_bfloat16* aP[2] = { hi ? hH : aggH, hi ? hL : aggL };
        char* dst0 = sm + st * STAGEB;
#pragma unroll
        for (int i = 0; i < 8; i++) {
            const int idx = i * 256 + tid;
            const int p = idx >> 9, r = (idx >> 2) & 127, j = idx & 3;
            const void* src;
            if (p < 2) {
                src = aP[p] + (size_t)(row0 + r) * KD + ka + j * 8;
            } else {
                const int c = col0 + r;
                const __nv_bfloat16* W;
                if (hi) W = ((p == 3) ? WhhL : WhhH)
                            + (size_t)((c < 768) ? c : c - 256) * KD + ka;
                else    W = ((p == 3) ? WfL : WfH) + (size_t)c * KD + ka;
                src = W + j * 8;
            }
            cpasync16(dst0 + p * PLANEB + r * (SA * 2) + j * 16, src);
        }
        asm volatile("cp.async.commit_group;" ::: "memory");
    };

    float acc[2][8][4];
#pragma unroll
    for (int mi = 0; mi < 2; mi++)
#pragma unroll
        for (int ni = 0; ni < 8; ni++)
#pragma unroll
            for (int j = 0; j < 4; j++) acc[mi][ni][j] = 0.0f;

    copy_stage(0, kbeg);
    for (int c = kbeg; c < kend; c++) {
        const int st = (c - kbeg) & 1;
        if (c + 1 < kend) { copy_stage(st ^ 1, c + 1);
            asm volatile("cp.async.wait_group 1;" ::: "memory");
        } else asm volatile("cp.async.wait_group 0;" ::: "memory");
        __syncthreads();
        GEMM_COMPUTE(sb + st * STAGEB);
        __syncthreads();
    }
#pragma unroll
    for (int mi = 0; mi < 2; mi++) {
        const int r = row0 + wm * 32 + mi * 16 + g;
#pragma unroll
        for (int ni = 0; ni < 8; ni++) {
            const int cc = col0 + wn * 64 + ni * 8 + tq * 2;
            const float b0 = cbias[cc], b1 = cbias[cc + 1];
            *(float2*)(C + (size_t)r * 1024 + cc) =
                make_float2(acc[mi][ni][0] + b0, acc[mi][ni][1] + b1);
            *(float2*)(C + (size_t)(r + 8) * 1024 + cc) =
                make_float2(acc[mi][ni][2] + b0, acc[mi][ni][3] + b1);
        }
    }
}

// ---------------- split helpers ---------------------------------------------
__device__ __forceinline__ void split1(float v, __nv_bfloat16& h, __nv_bfloat16& l) {
    h = __float2bfloat16(v);
    l = __float2bfloat16(v - __bfloat162float(h));
}

// ---------------- prep kernels -----------------------------------------------
__global__ void prep_x(const float* __restrict__ x,
                       __nv_bfloat16* __restrict__ xh, __nv_bfloat16* __restrict__ xl) {
    const int idx = blockIdx.x * 256 + threadIdx.x;
    if (idx >= NN * KD) return;
    const int row = idx >> 8, col = idx & 255;
    const float v = (row < NREAL && col < 200) ? x[row * 200 + col] : 0.0f;
    split1(v, xh[idx], xl[idx]);
}
__global__ void prep_wred(const float* __restrict__ W,
                          __nv_bfloat16* __restrict__ wh, __nv_bfloat16* __restrict__ wl) {
    const int idx = blockIdx.x * 256 + threadIdx.x;
    if (idx >= 256 * KD) return;
    const int n = idx >> 8, k = idx & 255;
    const float v = (k < 200) ? W[n * 200 + k] : 0.0f;
    split1(v, wh[idx], wl[idx]);
}
__global__ void prep_whh(const float* __restrict__ W,
                         __nv_bfloat16* __restrict__ wh, __nv_bfloat16* __restrict__ wl) {
    const int idx = blockIdx.x * 256 + threadIdx.x;
    if (idx >= 768 * KD) return;
    split1(W[idx], wh[idx], wl[idx]);
}
// Wfused[t][o][k] = sum_c W_ggc[t][k][c] * W_ih[o][c]
__global__ void __launch_bounds__(256)
prep_wfused(const float* __restrict__ Wih, const float* __restrict__ Wggc,
            __nv_bfloat16* __restrict__ fh, __nv_bfloat16* __restrict__ fl)
{
    __shared__ float sA[16][65];
    __shared__ float sB[16][65];
    const int tid = threadIdx.x;
    const int tx = tid & 15, ty = tid >> 4;
    const int k0 = blockIdx.x * 64, o0 = blockIdx.y * 64;
    const int t  = blockIdx.z;
    const float* Wg = Wggc + (size_t)t * 65536;

    float acc[4][4];
#pragma unroll
    for (int i = 0; i < 4; i++)
#pragma unroll
        for (int j = 0; j < 4; j++) acc[i][j] = 0.0f;

    for (int c0 = 0; c0 < 256; c0 += 16) {
#pragma unroll
        for (int i = 0; i < 4; i++) {
            const int idx = i * 256 + tid;
            const int oo = idx >> 4, cc = idx & 15;
            sA[cc][oo] = Wih[(size_t)(o0 + oo) * 256 + c0 + cc];
            sB[cc][oo] = Wg[(size_t)(k0 + oo) * 256 + c0 + cc];
        }
        __syncthreads();
#pragma unroll
        for (int c = 0; c < 16; c++) {
            float av[4], bv[4];
#pragma unroll
            for (int i = 0; i < 4; i++) av[i] = sA[c][ty * 4 + i];
#pragma unroll
            for (int j = 0; j < 4; j++) bv[j] = sB[c][tx * 4 + j];
#pragma unroll
            for (int i = 0; i < 4; i++)
#pragma unroll
                for (int j = 0; j < 4; j++)
                    acc[i][j] = fmaf(av[i], bv[j], acc[i][j]);
        }
        __syncthreads();
    }
#pragma unroll
    for (int i = 0; i < 4; i++) {
        const int o = o0 + ty * 4 + i;
#pragma unroll
        for (int j = 0; j < 4; j++) {
            const int k = k0 + tx * 4 + j;
            const size_t off = (size_t)t * 768 * KD + (size_t)o * KD + k;
            __nv_bfloat16 hh, ll;
            split1(acc[i][j], hh, ll);
            fh[off] = hh; fl[off] = ll;
        }
    }
}
__global__ void prep_cbias(const float* __restrict__ bih, const float* __restrict__ bhh,
                           float* __restrict__ cb) {
    const int c = blockIdx.x * 256 + threadIdx.x;
    if (c >= 1024) return;
    float v;
    if (c < 512)       v = bih[c] + bhh[c];
    else if (c < 768)  v = bih[c];
    else               v = bhh[c - 256];
    cb[c] = v;
}
__global__ void split_h(const float* __restrict__ h,
                        __nv_bfloat16* __restrict__ hh, __nv_bfloat16* __restrict__ hl) {
    const int idx = blockIdx.x * 256 + threadIdx.x;
    if (idx >= NN * HID) return;
    split1(h[idx], hh[idx], hl[idx]);
}

// ---------------- CSR build --------------------------------------------------
__global__ void hist_kernel(const int* __restrict__ ei, int* __restrict__ cnt) {
    const int e = blockIdx.x * 256 + threadIdx.x;
    if (e >= NE) return;
    atomicAdd(&cnt[ei[NE + e]], 1);
}
__global__ void scan_kernel(const int* __restrict__ cnt, int* __restrict__ rowptr) {
    __shared__ int s[1024];
    __shared__ int carryS;
    const int tid = threadIdx.x;
    if (tid == 0) { carryS = 0; rowptr[0] = 0; }
    __syncthreads();
    for (int base = 0; base < NN; base += 1024) {
        const int idx = base + tid;
        int v = (idx < NN) ? cnt[idx] : 0;
        s[tid] = v;
        __syncthreads();
        for (int off = 1; off < 1024; off <<= 1) {
            int t = (tid >= off) ? s[tid - off] : 0;
            __syncthreads();
            s[tid] += t;
            __syncthreads();
        }
        const int carry = carryS;
        if (idx < NN) rowptr[idx + 1] = carry + s[tid];
        __syncthreads();
        if (tid == 1023) carryS = carry + s[1023];
        __syncthreads();
    }
}
__global__ void copycur_kernel(const int* __restrict__ rowptr, int* __restrict__ cur) {
    const int i = blockIdx.x * 256 + threadIdx.x;
    if (i < NN) cur[i] = rowptr[i];
}
__global__ void fill_kernel(const int* __restrict__ ei, int* __restrict__ cur,
                            int* __restrict__ eidx) {
    const int e = blockIdx.x * 256 + threadIdx.x;
    if (e >= NE) return;
    const int pos = atomicAdd(&cur[ei[NE + e]], 1);
    eidx[pos] = ei[e];
}

// ---------------- aggregation: warp/dst-node gather of h -> bf16 planes ------
__global__ void agg_kernel(const float* __restrict__ h,
                           const int* __restrict__ rowptr, const int* __restrict__ eidx,
                           __nv_bfloat16* __restrict__ aggH, __nv_bfloat16* __restrict__ aggL)
{
    const int w = (blockIdx.x * blockDim.x + threadIdx.x) >> 5;
    const int lane = threadIdx.x & 31;
    if (w >= NN) return;
    const int beg = rowptr[w], end = rowptr[w + 1];
    float4 a0 = make_float4(0, 0, 0, 0), a1 = make_float4(0, 0, 0, 0);
    for (int i = beg; i < end; i++) {
        const int s = eidx[i];
        const float4* hr = (const float4*)(h + (size_t)s * 256);
        const float4 v0 = hr[lane * 2], v1 = hr[lane * 2 + 1];
        a0.x += v0.x; a0.y += v0.y; a0.z += v0.z; a0.w += v0.w;
        a1.x += v1.x; a1.y += v1.y; a1.z += v1.z; a1.w += v1.w;
    }
    const float vals[8] = {a0.x, a0.y, a0.z, a0.w, a1.x, a1.y, a1.z, a1.w};
    unsigned hb[4], lb[4];
#pragma unroll
    for (int q = 0; q < 4; q++) {
        __nv_bfloat16 h0, l0, h1, l1;
        split1(vals[2 * q], h0, l0);
        split1(vals[2 * q + 1], h1, l1);
        __nv_bfloat162 ph(h0, h1), pl(l0, l1);
        hb[q] = *(unsigned*)&ph;
        lb[q] = *(unsigned*)&pl;
    }
    *(uint4*)(aggH + (size_t)w * 256 + lane * 8) = make_uint4(hb[0], hb[1], hb[2], hb[3]);
    *(uint4*)(aggL + (size_t)w * 256 + lane * 8) = make_uint4(lb[0], lb[1], lb[2], lb[3]);
}

// ---------------- fused GRU (reads pre-summed gates) -------------------------
__device__ __forceinline__ float sigf(float x) { return 1.0f / (1.0f + __expf(-x)); }

__global__ void gru_kernel(const float* __restrict__ gates,
                           float* __restrict__ h,
                           __nv_bfloat16* __restrict__ hh, __nv_bfloat16* __restrict__ hl)
{
    const int idx = blockIdx.x * blockDim.x + threadIdx.x;
    if (idx >= NN * 64) return;
    const int row = idx >> 6, c = (idx & 63) * 4;
    const float* G = gates + (size_t)row * 1024;
    const float4 rs = *(const float4*)(G + c);
    const float4 zs = *(const float4*)(G + 256 + c);
    const float4 iv = *(const float4*)(G + 512 + c);
    const float4 hv2 = *(const float4*)(G + 768 + c);
    float4* H = (float4*)(h + (size_t)row * 256 + c);
    const float4 hv = *H;

    float4 o;
    { float r = sigf(rs.x), z = sigf(zs.x);
      float n = tanhf(iv.x + r * hv2.x); o.x = (1.0f - z) * n + z * hv.x; }
    { float r = sigf(rs.y), z = sigf(zs.y);
      float n = tanhf(iv.y + r * hv2.y); o.y = (1.0f - z) * n + z * hv.y; }
    { float r = sigf(rs.z), z = sigf(zs.z);
      float n = tanhf(iv.z + r * hv2.z); o.z = (1.0f - z) * n + z * hv.z; }
    { float r = sigf(rs.w), z = sigf(zs.w);
      float n = tanhf(iv.w + r * hv2.w); o.w = (1.0f - z) * n + z * hv.w; }
    *H = o;

    __nv_bfloat16 h0, l0, h1, l1, h2, l2, h3, l3;
    split1(o.x, h0, l0); split1(o.y, h1, l1);
    split1(o.z, h2, l2); split1(o.w, h3, l3);
    __nv_bfloat162 p01(h0, h1), p23(h2, h3), q01(l0, l1), q23(l2, l3);
    *(__nv_bfloat162*)(hh + (size_t)row * 256 + c)     = p01;
    *(__nv_bfloat162*)(hh + (size_t)row * 256 + c + 2) = p23;
    *(__nv_bfloat162*)(hl + (size_t)row * 256 + c)     = q01;
    *(__nv_bfloat162*)(hl + (size_t)row * 256 + c + 2) = q23;
}

// ---------------- head -------------------------------------------------------
__global__ void head_kernel(const float* __restrict__ h,
                            const float* __restrict__ W_lin,
                            const float* __restrict__ b_lin,
                            float* __restrict__ out, int N)
{
    const int gt = blockIdx.x * blockDim.x + threadIdx.x;
    const int node = gt >> 5;
    const int lane = gt & 31;
    if (node >= N) return;
    const float4* hr = (const float4*)(h + (size_t)node * HID);
    const float4* w0 = (const float4*)(W_lin);
    const float4* w1 = (const float4*)(W_lin + HID);
    float a0 = 0.0f, a1 = 0.0f;
#pragma unroll
    for (int it = 0; it < 2; it++) {
        const int i = lane + it * 32;
        float4 v = hr[i];
        v.x = fmaxf(v.x, 0.f); v.y = fmaxf(v.y, 0.f);
        v.z = fmaxf(v.z, 0.f); v.w = fmaxf(v.w, 0.f);
        const float4 x0 = w0[i], x1 = w1[i];
        a0 += v.x * x0.x + v.y * x0.y + v.z * x0.z + v.w * x0.w;
        a1 += v.x * x1.x + v.y * x1.y + v.z * x1.z + v.w * x1.w;
    }
#pragma unroll
    for (int off = 16; off > 0; off >>= 1) {
        a0 += __shfl_down_sync(0xffffffffu, a0, off);
        a1 += __shfl_down_sync(0xffffffffu, a1, off);
    }
    if (lane == 0) {
        const float o0 = a0 + b_lin[0];
        const float o1 = a1 + b_lin[1];
        const float mx = fmaxf(o0, o1);
        const float lse = mx + logf(expf(o0 - mx) + expf(o1 - mx));
        out[(size_t)node * 2 + 0] = o0 - lse;
        out[(size_t)node * 2 + 1] = o1 - lse;
    }
}

// ---------------- launch -----------------------------------------------------
extern "C" void kernel_launch(void* const* d_in, const int* in_sizes, int n_in,
                              void* d_out, int out_size)
{
    const float* x        = (const float*)d_in[0];
    const int*   ei       = (const int*)  d_in[1];
    const float* W_reduce = (const float*)d_in[3];
    const float* b_reduce = (const float*)d_in[4];
    const float* W_ggc    = (const float*)d_in[5];
    const float* W_ih     = (const float*)d_in[6];
    const float* W_hh     = (const float*)d_in[7];
    const float* b_ih     = (const float*)d_in[8];
    const float* b_hh     = (const float*)d_in[9];
    const float* W_lin    = (const float*)d_in[10];
    const float* b_lin    = (const float*)d_in[11];
    float* out = (float*)d_out;

    float *h, *gates, *cbias;
    __nv_bfloat16 *hH, *hL, *xH, *xL, *aggH, *aggL, *WfH, *WfL, *WhH, *WhL, *WrH, *WrL;
    int *cnt, *rowptr, *cur, *eidx;
    cudaGetSymbolAddress((void**)&h, g_h);
    cudaGetSymbolAddress((void**)&gates, g_gates);
    cudaGetSymbolAddress((void**)&cbias, g_cbias);
    cudaGetSymbolAddress((void**)&hH, g_hH);
    cudaGetSymbolAddress((void**)&hL, g_hL);
    cudaGetSymbolAddress((void**)&xH, g_xH);
    cudaGetSymbolAddress((void**)&xL, g_xL);
    cudaGetSymbolAddress((void**)&aggH, g_aggH);
    cudaGetSymbolAddress((void**)&aggL, g_aggL);
    cudaGetSymbolAddress((void**)&WfH, g_WfusH);
    cudaGetSymbolAddress((void**)&WfL, g_WfusL);
    cudaGetSymbolAddress((void**)&WhH, g_WhhH);
    cudaGetSymbolAddress((void**)&WhL, g_WhhL);
    cudaGetSymbolAddress((void**)&WrH, g_WredH);
    cudaGetSymbolAddress((void**)&WrL, g_WredL);
    cudaGetSymbolAddress((void**)&cnt, g_cnt);
    cudaGetSymbolAddress((void**)&rowptr, g_rowptr);
    cudaGetSymbolAddress((void**)&cur, g_cur);
    cudaGetSymbolAddress((void**)&eidx, g_eidx);

    cudaFuncSetAttribute(gemm_init, cudaFuncAttributeMaxDynamicSharedMemorySize, GSMEM);
    cudaFuncSetAttribute(gemm_step, cudaFuncAttributeMaxDynamicSharedMemorySize, GSMEM);

    // ---- preprocessing ----
    prep_x<<<(NN * KD + 255) / 256, 256>>>(x, xH, xL);
    prep_wred<<<(256 * KD + 255) / 256, 256>>>(W_reduce, WrH, WrL);
    prep_whh<<<(768 * KD + 255) / 256, 256>>>(W_hh, WhH, WhL);
    prep_wfused<<<dim3(4, 12, NSTEP), 256>>>(W_ih, W_ggc, WfH, WfL);
    prep_cbias<<<4, 256>>>(b_ih, b_hh, cbias);
    cudaMemsetAsync(cnt, 0, NN * sizeof(int));
    hist_kernel<<<(NE + 255) / 256, 256>>>(ei, cnt);
    scan_kernel<<<1, 1024>>>(cnt, rowptr);
    copycur_kernel<<<(NN + 255) / 256, 256>>>(rowptr, cur);
    fill_kernel<<<(NE + 255) / 256, 256>>>(ei, cur, eidx);

    const int MB = NN / 128;   // 391

    // h = x @ W_reduce^T + b_reduce
    gemm_init<<<dim3(2, MB), 256, GSMEM>>>(xH, xL, WrH, WrL, b_reduce, h, 256);
    split_h<<<(NN * HID + 255) / 256, 256>>>(h, hH, hL);

    for (int t = 0; t < NSTEP; t++) {
        agg_kernel<<<(NN * 32 + 255) / 256, 256>>>(h, rowptr, eidx, aggH, aggL);
        gemm_step<<<dim3(8, MB), 256, GSMEM>>>(
            aggH, aggL, hH, hL,
            WfH + (size_t)t * 768 * KD, WfL + (size_t)t * 768 * KD,
            WhH, WhL, cbias, gates);
        gru_kernel<<<(NN * 64 + 255) / 256, 256>>>(gates, h, hH, hL);
    }

    head_kernel<<<(NREAL * 32 + 255) / 256, 256>>>(h, W_lin, b_lin, out, NREAL);
}

// round 9
// speedup vs baseline: 3.6500x; 1.0192x over previous
#include <cuda_runtime.h>
#include <cuda_bf16.h>
#include <math.h>
#include <stdint.h>

#define NN      50048      // padded node count (391 * 128)
#define NREAL   50000
#define NE      300000
#define KD      256
#define HID     256
#define NSTEP   8
#define SCANB   ((NN + 1023) / 1024)   // 49

// ---------------- scratch (static device globals; no runtime alloc) ----------
__device__ float g_h    [NN * HID];
__device__ float g_gates[NN * 1024];       // [r_sum | z_sum | i_n | h_n]
__device__ __nv_bfloat16 g_hH[NN * KD],   g_hL[NN * KD];
__device__ __nv_bfloat16 g_xH[NN * KD],   g_xL[NN * KD];
__device__ __nv_bfloat16 g_aggH[NN * KD], g_aggL[NN * KD];
__device__ __nv_bfloat16 g_WfusH[NSTEP * 768 * KD], g_WfusL[NSTEP * 768 * KD];
__device__ __nv_bfloat16 g_WhhH[768 * KD], g_WhhL[768 * KD];
__device__ __nv_bfloat16 g_WredH[256 * KD], g_WredL[256 * KD];
__device__ __nv_bfloat16 g_WihH[768 * KD], g_WihL[768 * KD];
__device__ __nv_bfloat16 g_WgH[NSTEP * 256 * 256], g_WgL[NSTEP * 256 * 256];
__device__ float g_cbias[1024];
__device__ int g_cnt[NN], g_rowptr[NN + 1], g_cur[NN], g_eidx[NE];
__device__ int g_bsum[SCANB], g_boff[SCANB];

// ---------------- shared GEMM machinery --------------------------------------
#define BK    32
#define SA    40                       // smem row stride in bf16 elems (80B)
#define PLANEB (128 * SA * 2)          // 10240 B per plane
#define STAGEB (4 * PLANEB)            // 40960 B per stage
#define GSMEM  (2 * STAGEB)            // 81920 B

__device__ __forceinline__ void mma_bf16(float* c, const unsigned* a, const unsigned* b)
{
    asm volatile(
        "mma.sync.aligned.m16n8k16.row.col.f32.bf16.bf16.f32 "
        "{%0,%1,%2,%3}, {%4,%5,%6,%7}, {%8,%9}, {%0,%1,%2,%3};\n"
        : "+f"(c[0]), "+f"(c[1]), "+f"(c[2]), "+f"(c[3])
        : "r"(a[0]), "r"(a[1]), "r"(a[2]), "r"(a[3]), "r"(b[0]), "r"(b[1]));
}
__device__ __forceinline__ void ldsm4(unsigned* r, uint32_t addr)
{
    asm volatile("ldmatrix.sync.aligned.m8n8.x4.shared.b16 {%0,%1,%2,%3}, [%4];"
                 : "=r"(r[0]), "=r"(r[1]), "=r"(r[2]), "=r"(r[3]) : "r"(addr));
}
__device__ __forceinline__ void cpasync16(char* dst, const void* src)
{
    asm volatile("cp.async.cg.shared.global [%0], [%1], 16;"
                 :: "l"((uint64_t)__cvta_generic_to_shared(dst)), "l"(src) : "memory");
}

// Compute-core over a staged tile. Product-major issue order: each acc's
// 3 dependent HMMAs are separated by 4 independent ones (ILP for the scoreboard).
#define GEMM_COMPUTE(base)                                                     \
    do {                                                                       \
        _Pragma("unroll")                                                      \
        for (int ks = 0; ks < 2; ks++) {                                       \
            const uint32_t kso = ks * 32;                                      \
            unsigned aH[2][4], aL[2][4];                                       \
            ldsm4(aH[0], (base) + 0 * PLANEB + aoffH0 + kso);                  \
            ldsm4(aH[1], (base) + 0 * PLANEB + aoffH1 + kso);                  \
            ldsm4(aL[0], (base) + 1 * PLANEB + aoffH0 + kso);                  \
            ldsm4(aL[1], (base) + 1 * PLANEB + aoffH1 + kso);                  \
            _Pragma("unroll")                                                  \
            for (int ni2 = 0; ni2 < 8; ni2 += 2) {                             \
                unsigned bH[4], bL[4];                                         \
                const uint32_t bo = boff0 + (uint32_t)(ni2 * 8 * SA * 2) + kso;\
                ldsm4(bH, (base) + 2 * PLANEB + bo);                           \
                ldsm4(bL, (base) + 3 * PLANEB + bo);                           \
                _Pragma("unroll")                                              \
                for (int mi = 0; mi < 2; mi++)                                 \
                    _Pragma("unroll")                                          \
                    for (int q = 0; q < 2; q++)                                \
                        mma_bf16(acc[mi][ni2 + q], aH[mi], bH + q * 2);        \
                _Pragma("unroll")                                              \
                for (int mi = 0; mi < 2; mi++)                                 \
                    _Pragma("unroll")                                          \
                    for (int q = 0; q < 2; q++)                                \
                        mma_bf16(acc[mi][ni2 + q], aH[mi], bL + q * 2);        \
                _Pragma("unroll")                                              \
                for (int mi = 0; mi < 2; mi++)                                 \
                    _Pragma("unroll")                                          \
                    for (int q = 0; q < 2; q++)                                \
                        mma_bf16(acc[mi][ni2 + q], aL[mi], bH + q * 2);        \
            }                                                                  \
        }                                                                      \
    } while (0)

#define FRAG_SETUP()                                                           \
    const int tid  = threadIdx.x;                                              \
    const int lane = tid & 31;                                                 \
    const int warp = tid >> 5;                                                 \
    const int wm   = warp & 3;                                                 \
    const int wn   = warp >> 2;                                                \
    const int g    = lane >> 2;                                                \
    const int tq   = lane & 3;                                                 \
    const int a_row = wm * 32 + (lane & 15);                                   \
    const int a_kx  = (lane >> 4) * 16;                                        \
    const uint32_t aoffH0 = (uint32_t)(a_row * SA * 2 + a_kx);                 \
    const uint32_t aoffH1 = aoffH0 + 16 * SA * 2;                              \
    const int b_col = wn * 64 + (lane & 7) + ((lane >> 4) & 1) * 8;            \
    const int b_kx  = ((lane >> 3) & 1) * 16;                                  \
    const uint32_t boff0 = (uint32_t)(b_col * SA * 2 + b_kx)

#define ACC_INIT()                                                             \
    float acc[2][8][4];                                                        \
    _Pragma("unroll")                                                          \
    for (int mi = 0; mi < 2; mi++)                                             \
        _Pragma("unroll")                                                      \
        for (int ni = 0; ni < 8; ni++)                                         \
            _Pragma("unroll")                                                  \
            for (int j = 0; j < 4; j++) acc[mi][ni][j] = 0.0f

__device__ __forceinline__ void split1(float v, __nv_bfloat16& h, __nv_bfloat16& l) {
    h = __float2bfloat16(v);
    l = __float2bfloat16(v - __bfloat162float(h));
}

// ---------------- init GEMM: C = A@B^T + bias --------------------------------
__global__ void __launch_bounds__(256, 2)
gemm_init(const __nv_bfloat16* __restrict__ AH, const __nv_bfloat16* __restrict__ AL,
          const __nv_bfloat16* __restrict__ BH, const __nv_bfloat16* __restrict__ BL,
          const float* __restrict__ bias, float* __restrict__ C, int ldc)
{
    extern __shared__ char sm[];
    const uint32_t sb = (uint32_t)__cvta_generic_to_shared(sm);
    FRAG_SETUP();
    const int row0 = blockIdx.y * 128, col0 = blockIdx.x * 128;
    const __nv_bfloat16* gp[4] = {AH, AL, BH, BL};

    auto copy_stage = [&](int st, int kc) {
        const int k0 = kc * BK;
        char* dst0 = sm + st * STAGEB;
#pragma unroll
        for (int i = 0; i < 8; i++) {
            const int idx = i * 256 + tid;
            const int p = idx >> 9, r = (idx >> 2) & 127, j = idx & 3;
            const int grow = ((p < 2) ? row0 : col0) + r;
            cpasync16(dst0 + p * PLANEB + r * (SA * 2) + j * 16,
                      gp[p] + (size_t)grow * KD + k0 + j * 8);
        }
        asm volatile("cp.async.commit_group;" ::: "memory");
    };

    ACC_INIT();
    copy_stage(0, 0);
    const int NCHUNK = KD / BK;
    for (int c = 0; c < NCHUNK; c++) {
        const int st = c & 1;
        if (c + 1 < NCHUNK) { copy_stage(st ^ 1, c + 1);
            asm volatile("cp.async.wait_group 1;" ::: "memory");
        } else asm volatile("cp.async.wait_group 0;" ::: "memory");
        __syncthreads();
        GEMM_COMPUTE(sb + st * STAGEB);
        __syncthreads();
    }
#pragma unroll
    for (int mi = 0; mi < 2; mi++) {
        const int r = row0 + wm * 32 + mi * 16 + g;
#pragma unroll
        for (int ni = 0; ni < 8; ni++) {
            const int cc = col0 + wn * 64 + ni * 8 + tq * 2;
            const float b0 = bias[cc], b1 = bias[cc + 1];
            *(float2*)(C + (size_t)r * ldc + cc) =
                make_float2(acc[mi][ni][0] + b0, acc[mi][ni][1] + b1);
            *(float2*)(C + (size_t)(r + 8) * ldc + cc) =
                make_float2(acc[mi][ni][2] + b0, acc[mi][ni][3] + b1);
        }
    }
}

// ---------------- Wfused GEMM: Wfus[t] = Wih @ Wg_t^T, split-written ---------
// grid (2, 6, 8): col0 = bx*128 (k), row0 = by*128 (o), t = bz. K = 256 (c).
__global__ void __launch_bounds__(256, 2)
gemm_wfus(const __nv_bfloat16* __restrict__ AH, const __nv_bfloat16* __restrict__ AL,
          const __nv_bfloat16* __restrict__ BHall, const __nv_bfloat16* __restrict__ BLall,
          __nv_bfloat16* __restrict__ fh, __nv_bfloat16* __restrict__ fl)
{
    extern __shared__ char sm[];
    const uint32_t sb = (uint32_t)__cvta_generic_to_shared(sm);
    FRAG_SETUP();
    const int row0 = blockIdx.y * 128, col0 = blockIdx.x * 128;
    const int t = blockIdx.z;
    const __nv_bfloat16* gp[4] = {AH, AL, BHall + (size_t)t * 65536,
                                  BLall + (size_t)t * 65536};

    auto copy_stage = [&](int st, int kc) {
        const int k0 = kc * BK;
        char* dst0 = sm + st * STAGEB;
#pragma unroll
        for (int i = 0; i < 8; i++) {
            const int idx = i * 256 + tid;
            const int p = idx >> 9, r = (idx >> 2) & 127, j = idx & 3;
            const int grow = ((p < 2) ? row0 : col0) + r;
            cpasync16(dst0 + p * PLANEB + r * (SA * 2) + j * 16,
                      gp[p] + (size_t)grow * 256 + k0 + j * 8);
        }
        asm volatile("cp.async.commit_group;" ::: "memory");
    };

    ACC_INIT();
    copy_stage(0, 0);
    for (int c = 0; c < 8; c++) {
        const int st = c & 1;
        if (c + 1 < 8) { copy_stage(st ^ 1, c + 1);
            asm volatile("cp.async.wait_group 1;" ::: "memory");
        } else asm volatile("cp.async.wait_group 0;" ::: "memory");
        __syncthreads();
        GEMM_COMPUTE(sb + st * STAGEB);
        __syncthreads();
    }
    const size_t tb = (size_t)t * 768 * KD;
#pragma unroll
    for (int mi = 0; mi < 2; mi++) {
        const int r = row0 + wm * 32 + mi * 16 + g;
#pragma unroll
        for (int ni = 0; ni < 8; ni++) {
            const int cc = col0 + wn * 64 + ni * 8 + tq * 2;
#pragma unroll
            for (int j = 0; j < 4; j++) {
                const int rr = (j < 2) ? r : r + 8;
                const int kk = cc + (j & 1);
                __nv_bfloat16 hh, ll;
                split1(acc[mi][ni][j], hh, ll);
                fh[tb + (size_t)rr * KD + kk] = hh;
                fl[tb + (size_t)rr * KD + kk] = ll;
            }
        }
    }
}

// ---------------- step GEMM: gates = [agg|h] @ B'^T + cbias ------------------
__global__ void __launch_bounds__(256, 2)
gemm_step(const __nv_bfloat16* __restrict__ aggH, const __nv_bfloat16* __restrict__ aggL,
          const __nv_bfloat16* __restrict__ hH,   const __nv_bfloat16* __restrict__ hL,
          const __nv_bfloat16* __restrict__ WfH,  const __nv_bfloat16* __restrict__ WfL,
          const __nv_bfloat16* __restrict__ WhhH, const __nv_bfloat16* __restrict__ WhhL,
          const float* __restrict__ cbias, float* __restrict__ C)
{
    extern __shared__ char sm[];
    const uint32_t sb = (uint32_t)__cvta_generic_to_shared(sm);
    FRAG_SETUP();
    const int bx   = blockIdx.x;
    const int row0 = blockIdx.y * 128, col0 = bx * 128;

    int kbeg, kend;
    if (bx < 4)      { kbeg = 0; kend = 16; }
    else if (bx < 6) { kbeg = 0; kend = 8;  }
    else             { kbeg = 8; kend = 16; }

    auto copy_stage = [&](int st, int kc) {
        const int k0 = kc * BK;
        const bool hi = k0 >= 256;
        const int ka = hi ? k0 - 256 : k0;
        const __nv_bfloat16* aP[2] = { hi ? hH : aggH, hi ? hL : aggL };
        char* dst0 = sm + st * STAGEB;
#pragma unroll
        for (int i = 0; i < 8; i++) {
            const int idx = i * 256 + tid;
            const int p = idx >> 9, r = (idx >> 2) & 127, j = idx & 3;
            const void* src;
            if (p < 2) {
                src = aP[p] + (size_t)(row0 + r) * KD + ka + j * 8;
            } else {
                const int c = col0 + r;
                const __nv_bfloat16* W;
                if (hi) W = ((p == 3) ? WhhL : WhhH)
                            + (size_t)((c < 768) ? c : c - 256) * KD + ka;
                else    W = ((p == 3) ? WfL : WfH) + (size_t)c * KD + ka;
                src = W + j * 8;
            }
            cpasync16(dst0 + p * PLANEB + r * (SA * 2) + j * 16, src);
        }
        asm volatile("cp.async.commit_group;" ::: "memory");
    };

    ACC_INIT();
    copy_stage(0, kbeg);
    for (int c = kbeg; c < kend; c++) {
        const int st = (c - kbeg) & 1;
        if (c + 1 < kend) { copy_stage(st ^ 1, c + 1);
            asm volatile("cp.async.wait_group 1;" ::: "memory");
        } else asm volatile("cp.async.wait_group 0;" ::: "memory");
        __syncthreads();
        GEMM_COMPUTE(sb + st * STAGEB);
        __syncthreads();
    }
#pragma unroll
    for (int mi = 0; mi < 2; mi++) {
        const int r = row0 + wm * 32 + mi * 16 + g;
#pragma unroll
        for (int ni = 0; ni < 8; ni++) {
            const int cc = col0 + wn * 64 + ni * 8 + tq * 2;
            const float b0 = cbias[cc], b1 = cbias[cc + 1];
            *(float2*)(C + (size_t)r * 1024 + cc) =
                make_float2(acc[mi][ni][0] + b0, acc[mi][ni][1] + b1);
            *(float2*)(C + (size_t)(r + 8) * 1024 + cc) =
                make_float2(acc[mi][ni][2] + b0, acc[mi][ni][3] + b1);
        }
    }
}

// ---------------- prep kernels -----------------------------------------------
__global__ void prep_x(const float* __restrict__ x,
                       __nv_bfloat16* __restrict__ xh, __nv_bfloat16* __restrict__ xl) {
    const int idx = blockIdx.x * 256 + threadIdx.x;
    if (idx >= NN * KD) return;
    const int row = idx >> 8, col = idx & 255;
    const float v = (row < NREAL && col < 200) ? x[row * 200 + col] : 0.0f;
    split1(v, xh[idx], xl[idx]);
}
__global__ void prep_wred(const float* __restrict__ W,
                          __nv_bfloat16* __restrict__ wh, __nv_bfloat16* __restrict__ wl) {
    const int idx = blockIdx.x * 256 + threadIdx.x;
    if (idx >= 256 * KD) return;
    const int n = idx >> 8, k = idx & 255;
    const float v = (k < 200) ? W[n * 200 + k] : 0.0f;
    split1(v, wh[idx], wl[idx]);
}
__global__ void prep_split(const float* __restrict__ W, int n,
                           __nv_bfloat16* __restrict__ wh, __nv_bfloat16* __restrict__ wl) {
    const int idx = blockIdx.x * 256 + threadIdx.x;
    if (idx >= n) return;
    split1(W[idx], wh[idx], wl[idx]);
}
__global__ void prep_cbias(const float* __restrict__ bih, const float* __restrict__ bhh,
                           float* __restrict__ cb) {
    const int c = blockIdx.x * 256 + threadIdx.x;
    if (c >= 1024) return;
    float v;
    if (c < 512)       v = bih[c] + bhh[c];
    else if (c < 768)  v = bih[c];
    else               v = bhh[c - 256];
    cb[c] = v;
}
__global__ void split_h(const float* __restrict__ h,
                        __nv_bfloat16* __restrict__ hh, __nv_bfloat16* __restrict__ hl) {
    const int idx = blockIdx.x * 256 + threadIdx.x;
    if (idx >= NN * HID) return;
    split1(h[idx], hh[idx], hl[idx]);
}

// ---------------- CSR build (parallel 3-phase scan) --------------------------
__global__ void hist_kernel(const int* __restrict__ ei, int* __restrict__ cnt) {
    const int e = blockIdx.x * 256 + threadIdx.x;
    if (e >= NE) return;
    atomicAdd(&cnt[ei[NE + e]], 1);
}
__global__ void scan_local(const int* __restrict__ cnt, int* __restrict__ rowptr,
                           int* __restrict__ bsum) {
    __shared__ int s[1024];
    const int tid = threadIdx.x;
    const int idx = blockIdx.x * 1024 + tid;
    int v = (idx < NN) ? cnt[idx] : 0;
    s[tid] = v;
    __syncthreads();
#pragma unroll
    for (int off = 1; off < 1024; off <<= 1) {
        int t = (tid >= off) ? s[tid - off] : 0;
        __syncthreads();
        s[tid] += t;
        __syncthreads();
    }
    if (idx < NN) rowptr[idx + 1] = s[tid];
    if (tid == 1023) bsum[blockIdx.x] = s[1023];
}
__global__ void scan_bsum(const int* __restrict__ bsum, int* __restrict__ boff) {
    if (threadIdx.x == 0) {
        int acc = 0;
        for (int i = 0; i < SCANB; i++) { boff[i] = acc; acc += bsum[i]; }
    }
}
__global__ void scan_add(int* __restrict__ rowptr, const int* __restrict__ boff) {
    const int idx = blockIdx.x * 1024 + threadIdx.x;
    if (idx == 0) rowptr[0] = 0;
    if (idx < NN) rowptr[idx + 1] += boff[blockIdx.x];
}
__global__ void copycur_kernel(const int* __restrict__ rowptr, int* __restrict__ cur) {
    const int i = blockIdx.x * 256 + threadIdx.x;
    if (i < NN) cur[i] = rowptr[i];
}
__global__ void fill_kernel(const int* __restrict__ ei, int* __restrict__ cur,
                            int* __restrict__ eidx) {
    const int e = blockIdx.x * 256 + threadIdx.x;
    if (e >= NE) return;
    const int pos = atomicAdd(&cur[ei[NE + e]], 1);
    eidx[pos] = ei[e];
}

// ---------------- aggregation: warp/dst-node gather of h -> bf16 planes ------
__global__ void agg_kernel(const float* __restrict__ h,
                           const int* __restrict__ rowptr, const int* __restrict__ eidx,
                           __nv_bfloat16* __restrict__ aggH, __nv_bfloat16* __restrict__ aggL)
{
    const int w = (blockIdx.x * blockDim.x + threadIdx.x) >> 5;
    const int lane = threadIdx.x & 31;
    if (w >= NN) return;
    const int beg = rowptr[w], end = rowptr[w + 1];
    float4 a0 = make_float4(0, 0, 0, 0), a1 = make_float4(0, 0, 0, 0);
    for (int i = beg; i < end; i++) {
        const int s = eidx[i];
        const float4* hr = (const float4*)(h + (size_t)s * 256);
        const float4 v0 = hr[lane * 2], v1 = hr[lane * 2 + 1];
        a0.x += v0.x; a0.y += v0.y; a0.z += v0.z; a0.w += v0.w;
        a1.x += v1.x; a1.y += v1.y; a1.z += v1.z; a1.w += v1.w;
    }
    const float vals[8] = {a0.x, a0.y, a0.z, a0.w, a1.x, a1.y, a1.z, a1.w};
    unsigned hb[4], lb[4];
#pragma unroll
    for (int q = 0; q < 4; q++) {
        __nv_bfloat16 h0, l0, h1, l1;
        split1(vals[2 * q], h0, l0);
        split1(vals[2 * q + 1], h1, l1);
        __nv_bfloat162 ph(h0, h1), pl(l0, l1);
        hb[q] = *(unsigned*)&ph;
        lb[q] = *(unsigned*)&pl;
    }
    *(uint4*)(aggH + (size_t)w * 256 + lane * 8) = make_uint4(hb[0], hb[1], hb[2], hb[3]);
    *(uint4*)(aggL + (size_t)w * 256 + lane * 8) = make_uint4(lb[0], lb[1], lb[2], lb[3]);
}

// ---------------- fused GRU (reads pre-summed gates) -------------------------
__device__ __forceinline__ float sigf(float x) { return 1.0f / (1.0f + __expf(-x)); }

__global__ void gru_kernel(const float* __restrict__ gates,
                           float* __restrict__ h,
                           __nv_bfloat16* __restrict__ hh, __nv_bfloat16* __restrict__ hl)
{
    const int idx = blockIdx.x * blockDim.x + threadIdx.x;
    if (idx >= NN * 64) return;
    const int row = idx >> 6, c = (idx & 63) * 4;
    const float* G = gates + (size_t)row * 1024;
    const float4 rs = *(const float4*)(G + c);
    const float4 zs = *(const float4*)(G + 256 + c);
    const float4 iv = *(const float4*)(G + 512 + c);
    const float4 hv2 = *(const float4*)(G + 768 + c);
    float4* H = (float4*)(h + (size_t)row * 256 + c);
    const float4 hv = *H;

    float4 o;
    { float r = sigf(rs.x), z = sigf(zs.x);
      float n = tanhf(iv.x + r * hv2.x); o.x = (1.0f - z) * n + z * hv.x; }
    { float r = sigf(rs.y), z = sigf(zs.y);
      float n = tanhf(iv.y + r * hv2.y); o.y = (1.0f - z) * n + z * hv.y; }
    { float r = sigf(rs.z), z = sigf(zs.z);
      float n = tanhf(iv.z + r * hv2.z); o.z = (1.0f - z) * n + z * hv.z; }
    { float r = sigf(rs.w), z = sigf(zs.w);
      float n = tanhf(iv.w + r * hv2.w); o.w = (1.0f - z) * n + z * hv.w; }
    *H = o;

    __nv_bfloat16 h0, l0, h1, l1, h2, l2, h3, l3;
    split1(o.x, h0, l0); split1(o.y, h1, l1);
    split1(o.z, h2, l2); split1(o.w, h3, l3);
    __nv_bfloat162 p01(h0, h1), p23(h2, h3), q01(l0, l1), q23(l2, l3);
    *(__nv_bfloat162*)(hh + (size_t)row * 256 + c)     = p01;
    *(__nv_bfloat162*)(hh + (size_t)row * 256 + c + 2) = p23;
    *(__nv_bfloat162*)(hl + (size_t)row * 256 + c)     = q01;
    *(__nv_bfloat162*)(hl + (size_t)row * 256 + c + 2) = q23;
}

// ---------------- head -------------------------------------------------------
__global__ void head_kernel(const float* __restrict__ h,
                            const float* __restrict__ W_lin,
                            const float* __restrict__ b_lin,
                            float* __restrict__ out, int N)
{
    const int gt = blockIdx.x * blockDim.x + threadIdx.x;
    const int node = gt >> 5;
    const int lane = gt & 31;
    if (node >= N) return;
    const float4* hr = (const float4*)(h + (size_t)node * HID);
    const float4* w0 = (const float4*)(W_lin);
    const float4* w1 = (const float4*)(W_lin + HID);
    float a0 = 0.0f, a1 = 0.0f;
#pragma unroll
    for (int it = 0; it < 2; it++) {
        const int i = lane + it * 32;
        float4 v = hr[i];
        v.x = fmaxf(v.x, 0.f); v.y = fmaxf(v.y, 0.f);
        v.z = fmaxf(v.z, 0.f); v.w = fmaxf(v.w, 0.f);
        const float4 x0 = w0[i], x1 = w1[i];
        a0 += v.x * x0.x + v.y * x0.y + v.z * x0.z + v.w * x0.w;
        a1 += v.x * x1.x + v.y * x1.y + v.z * x1.z + v.w * x1.w;
    }
#pragma unroll
    for (int off = 16; off > 0; off >>= 1) {
        a0 += __shfl_down_sync(0xffffffffu, a0, off);
        a1 += __shfl_down_sync(0xffffffffu, a1, off);
    }
    if (lane == 0) {
        const float o0 = a0 + b_lin[0];
        const float o1 = a1 + b_lin[1];
        const float mx = fmaxf(o0, o1);
        const float lse = mx + logf(expf(o0 - mx) + expf(o1 - mx));
        out[(size_t)node * 2 + 0] = o0 - lse;
        out[(size_t)node * 2 + 1] = o1 - lse;
    }
}

// ---------------- launch -----------------------------------------------------
extern "C" void kernel_launch(void* const* d_in, const int* in_sizes, int n_in,
                              void* d_out, int out_size)
{
    const float* x        = (const float*)d_in[0];
    const int*   ei       = (const int*)  d_in[1];
    const float* W_reduce = (const float*)d_in[3];
    const float* b_reduce = (const float*)d_in[4];
    const float* W_ggc    = (const float*)d_in[5];
    const float* W_ih     = (const float*)d_in[6];
    const float* W_hh     = (const float*)d_in[7];
    const float* b_ih     = (const float*)d_in[8];
    const float* b_hh     = (const float*)d_in[9];
    const float* W_lin    = (const float*)d_in[10];
    const float* b_lin    = (const float*)d_in[11];
    float* out = (float*)d_out;

    float *h, *gates, *cbias;
    __nv_bfloat16 *hH, *hL, *xH, *xL, *aggH, *aggL, *WfH, *WfL, *WhH, *WhL, *WrH, *WrL;
    __nv_bfloat16 *WiH, *WiL, *WgH, *WgL;
    int *cnt, *rowptr, *cur, *eidx, *bsum, *boff;
    cudaGetSymbolAddress((void**)&h, g_h);
    cudaGetSymbolAddress((void**)&gates, g_gates);
    cudaGetSymbolAddress((void**)&cbias, g_cbias);
    cudaGetSymbolAddress((void**)&hH, g_hH);
    cudaGetSymbolAddress((void**)&hL, g_hL);
    cudaGetSymbolAddress((void**)&xH, g_xH);
    cudaGetSymbolAddress((void**)&xL, g_xL);
    cudaGetSymbolAddress((void**)&aggH, g_aggH);
    cudaGetSymbolAddress((void**)&aggL, g_aggL);
    cudaGetSymbolAddress((void**)&WfH, g_WfusH);
    cudaGetSymbolAddress((void**)&WfL, g_WfusL);
    cudaGetSymbolAddress((void**)&WhH, g_WhhH);
    cudaGetSymbolAddress((void**)&WhL, g_WhhL);
    cudaGetSymbolAddress((void**)&WrH, g_WredH);
    cudaGetSymbolAddress((void**)&WrL, g_WredL);
    cudaGetSymbolAddress((void**)&WiH, g_WihH);
    cudaGetSymbolAddress((void**)&WiL, g_WihL);
    cudaGetSymbolAddress((void**)&WgH, g_WgH);
    cudaGetSymbolAddress((void**)&WgL, g_WgL);
    cudaGetSymbolAddress((void**)&cnt, g_cnt);
    cudaGetSymbolAddress((void**)&rowptr, g_rowptr);
    cudaGetSymbolAddress((void**)&cur, g_cur);
    cudaGetSymbolAddress((void**)&eidx, g_eidx);
    cudaGetSymbolAddress((void**)&bsum, g_bsum);
    cudaGetSymbolAddress((void**)&boff, g_boff);

    cudaFuncSetAttribute(gemm_init, cudaFuncAttributeMaxDynamicSharedMemorySize, GSMEM);
    cudaFuncSetAttribute(gemm_step, cudaFuncAttributeMaxDynamicSharedMemorySize, GSMEM);
    cudaFuncSetAttribute(gemm_wfus, cudaFuncAttributeMaxDynamicSharedMemorySize, GSMEM);

    // ---- preprocessing ----
    prep_x<<<(NN * KD + 255) / 256, 256>>>(x, xH, xL);
    prep_wred<<<(256 * KD + 255) / 256, 256>>>(W_reduce, WrH, WrL);
    prep_split<<<(768 * KD + 255) / 256, 256>>>(W_hh, 768 * KD, WhH, WhL);
    prep_split<<<(768 * KD + 255) / 256, 256>>>(W_ih, 768 * KD, WiH, WiL);
    prep_split<<<(NSTEP * 65536 + 255) / 256, 256>>>(W_ggc, NSTEP * 65536, WgH, WgL);
    gemm_wfus<<<dim3(2, 6, NSTEP), 256, GSMEM>>>(WiH, WiL, WgH, WgL, WfH, WfL);
    prep_cbias<<<4, 256>>>(b_ih, b_hh, cbias);
    cudaMemsetAsync(cnt, 0, NN * sizeof(int));
    hist_kernel<<<(NE + 255) / 256, 256>>>(ei, cnt);
    scan_local<<<SCANB, 1024>>>(cnt, rowptr, bsum);
    scan_bsum<<<1, 32>>>(bsum, boff);
    scan_add<<<SCANB, 1024>>>(rowptr, boff);
    copycur_kernel<<<(NN + 255) / 256, 256>>>(rowptr, cur);
    fill_kernel<<<(NE + 255) / 256, 256>>>(ei, cur, eidx);

    const int MB = NN / 128;   // 391

    // h = x @ W_reduce^T + b_reduce
    gemm_init<<<dim3(2, MB), 256, GSMEM>>>(xH, xL, WrH, WrL, b_reduce, h, 256);
    split_h<<<(NN * HID + 255) / 256, 256>>>(h, hH, hL);

    for (int t = 0; t < NSTEP; t++) {
        agg_kernel<<<(NN * 32 + 255) / 256, 256>>>(h, rowptr, eidx, aggH, aggL);
        gemm_step<<<dim3(8, MB), 256, GSMEM>>>(
            aggH, aggL, hH, hL,
            WfH + (size_t)t * 768 * KD, WfL + (size_t)t * 768 * KD,
            WhH, WhL, cbias, gates);
        gru_kernel<<<(NN * 64 + 255) / 256, 256>>>(gates, h, hH, hL);
    }

    head_kernel<<<(NREAL * 32 + 255) / 256, 256>>>(h, W_lin, b_lin, out, NREAL);
}